// round 11
// baseline (speedup 1.0000x reference)
#include <cuda_runtime.h>
#include <cuda_fp16.h>

#define NN  100000
#define EE  3200000
#define GRID_B 592          // 4 blocks/SM on 148 SMs; all co-resident
#define CHUNK 169           // ceil(NN / GRID_B)

typedef unsigned long long u64;
typedef unsigned int u32;

// ---------------- scratch (static device globals) ---------------------------
__device__ int   g_degi[NN];
__device__ float g_dinv[NN];
__device__ int   g_off[NN + 1];
__device__ int   g_cur[NN];
__device__ int   g_csrc[EE];
__device__ float g_h1s[NN * 32];    // x@init_w1 (fp32, from gemm)
__device__ float g_root1[NN * 32];  // x@root_w1 (fp32)
__device__ u64   g_h1sh[NN * 8];    // half-packed dinv[n]*h1s rows (64B/row)
__device__ u64   g_hsh[NN * 4];     // half-packed dinv[n]*h rows   (32B/row)
__device__ float g_aggh[NN * 16];   // dinv[d] * sum_src hs[src] (fp32)
__device__ int   g_bsum[640];
__device__ u32   g_barc;            // software grid-barrier counter (monotonic)

// ---------------- streams/events (created at image load, before harness) ----
struct HxStreams {
    cudaStream_t s2 = nullptr;
    cudaEvent_t ev_fork = nullptr, ev_build = nullptr, ev_join = nullptr;
    bool ok = false;
    HxStreams() {
        ok = (cudaStreamCreateWithFlags(&s2, cudaStreamNonBlocking) == cudaSuccess) &&
             (cudaEventCreateWithFlags(&ev_fork, cudaEventDisableTiming) == cudaSuccess) &&
             (cudaEventCreateWithFlags(&ev_build, cudaEventDisableTiming) == cudaSuccess) &&
             (cudaEventCreateWithFlags(&ev_join, cudaEventDisableTiming) == cudaSuccess);
    }
};
static HxStreams g_hx;

// ---------------- packed f32x2 helpers ---------------------------------------
__device__ __forceinline__ u64 ffma2(u64 a, u64 b, u64 c) {
    u64 d;
    asm("fma.rn.f32x2 %0, %1, %2, %3;" : "=l"(d) : "l"(a), "l"(b), "l"(c));
    return d;
}
__device__ __forceinline__ u64 pack2(float lo, float hi) {
    u64 r;
    asm("mov.b64 %0, {%1, %2};" : "=l"(r) : "f"(lo), "f"(hi));
    return r;
}
__device__ __forceinline__ void unpack2(u64 v, float& lo, float& hi) {
    asm("mov.b64 {%0, %1}, %2;" : "=f"(lo), "=f"(hi) : "l"(v));
}

// half helpers: u64 <-> 4 floats
__device__ __forceinline__ u64 pack_h4(float a, float b, float c, float d) {
    __half2 lo = __floats2half2_rn(a, b);
    __half2 hi = __floats2half2_rn(c, d);
    u32 ulo = *reinterpret_cast<u32*>(&lo);
    u32 uhi = *reinterpret_cast<u32*>(&hi);
    return (u64)ulo | ((u64)uhi << 32);
}
__device__ __forceinline__ void unpack_h4(u64 v, float4& f) {
    u32 ulo = (u32)v, uhi = (u32)(v >> 32);
    __half2 hlo = *reinterpret_cast<__half2*>(&ulo);
    __half2 hhi = *reinterpret_cast<__half2*>(&uhi);
    float2 a = __half22float2(hlo);
    float2 b = __half22float2(hhi);
    f.x = a.x; f.y = a.y; f.z = b.x; f.w = b.y;
}

// ---------------- software grid barrier (all GRID_B blocks resident) --------
__device__ __forceinline__ void gbar() {
    __syncthreads();
    if (threadIdx.x == 0) {
        __threadfence();
        u32 arrive = atomicAdd(&g_barc, 1u);
        u32 goal = (arrive / GRID_B + 1u) * GRID_B;
        while (true) {
            u32 v;
            asm volatile("ld.acquire.gpu.u32 %0, [%1];" : "=r"(v) : "l"(&g_barc));
            if (v >= goal) break;
        }
    }
    __syncthreads();
}

// ---------------- K: fused CSR build (zero+hist+dinv+scan+csr) ---------------
// ONE persistent kernel; enqueued FIRST so all 592 blocks are resident before
// gemm1 fills the remaining SM slots (barrier deadlock-safe).
__global__ void __launch_bounds__(256) k_build(const int* __restrict__ ei) {
    int t = threadIdx.x, b = blockIdx.x;
    int gtid = b * 256 + t;
    const int stride = GRID_B * 256;

    // phase 0: zero degree histogram
    for (int i = gtid; i < NN; i += stride) g_degi[i] = 0;
    gbar();

    // phase 1: degree histogram (int4 vectorized)
    for (int i = gtid; i < EE / 4; i += stride) {
        int4 d = *(const int4*)&ei[EE + i * 4];
        if ((unsigned)d.x < NN) atomicAdd(&g_degi[d.x], 1);
        if ((unsigned)d.y < NN) atomicAdd(&g_degi[d.y], 1);
        if ((unsigned)d.z < NN) atomicAdd(&g_degi[d.z], 1);
        if ((unsigned)d.w < NN) atomicAdd(&g_degi[d.w], 1);
    }
    gbar();

    // phase 2a: block-local inclusive scan over this block's CHUNK nodes
    __shared__ int sA[256], sB[256];
    int base = b * CHUNK;
    int node = base + t;
    int deg = (t < CHUNK && node < NN) ? g_degi[node] : 0;
    sA[t] = deg;
    __syncthreads();
    int* src = sA;
    int* dst = sB;
#pragma unroll
    for (int d = 1; d < 256; d <<= 1) {
        dst[t] = src[t] + ((t >= d) ? src[t - d] : 0);
        __syncthreads();
        int* tmp = src; src = dst; dst = tmp;
    }
    int incl = src[t];
    int excl = incl - deg;
    if (t == 0) g_bsum[b] = src[255];
    gbar();

    // phase 2b: block offset = sum of preceding block totals (thread 0)
    __shared__ int s_off;
    if (t == 0) {
        int off = 0;
        for (int j = 0; j < b; j++) off += g_bsum[j];
        s_off = off;
    }
    __syncthreads();

    // phase 2c: write offsets, cursors, dinv
    if (t < CHUNK && node < NN) {
        int o = s_off + excl;
        g_off[node] = o;
        g_cur[node] = o;
        g_dinv[node] = (deg > 0) ? rsqrtf((float)deg) : 0.0f;
    }
    if (b == 0 && t == 0) g_off[NN] = EE;
    gbar();

    // phase 3: CSR scatter (src grouped by dst)
    for (int i = gtid; i < EE / 4; i += stride) {
        int4 s = *(const int4*)&ei[i * 4];
        int4 d = *(const int4*)&ei[EE + i * 4];
        if ((unsigned)d.x < NN) g_csrc[atomicAdd(&g_cur[d.x], 1)] = s.x;
        if ((unsigned)d.y < NN) g_csrc[atomicAdd(&g_cur[d.y], 1)] = s.y;
        if ((unsigned)d.z < NN) g_csrc[atomicAdd(&g_cur[d.z], 1)] = s.z;
        if ((unsigned)d.w < NN) g_csrc[atomicAdd(&g_cur[d.w], 1)] = s.w;
    }
}

// ---------------- GEMM1 (R4 champion variant, 85us measured) -----------------
// tile: 128 nodes x 64 outputs, 256 threads; thread = 8 rows x 4 cols (f32x2)
__global__ void __launch_bounds__(256) k_gemm1(const float* __restrict__ x,
                                               const float* __restrict__ wi,
                                               const float* __restrict__ wr) {
    __shared__ float xs[128 * 68];
    __shared__ float ws[64 * 64];
    int tid = threadIdx.x;
    int nb = blockIdx.x * 128;
    int co = tid & 15;   // output group: cols co*4 .. co*4+3
    int rn = tid >> 4;   // row group:    rows rn*8 .. rn*8+7

    u64 acc[8][2];
#pragma unroll
    for (int i = 0; i < 8; i++) { acc[i][0] = 0ull; acc[i][1] = 0ull; }

    for (int fc = 0; fc < 256; fc += 64) {
#pragma unroll
        for (int j = 0; j < 8; j++) {
            int idx = tid + 256 * j;
            int r = idx >> 4;
            int c4 = (idx & 15) * 4;
            float4 v = make_float4(0.f, 0.f, 0.f, 0.f);
            int node = nb + r;
            if (node < NN) v = *(const float4*)&x[node * 256 + fc + c4];
            *(float4*)&xs[r * 68 + c4] = v;
        }
#pragma unroll
        for (int j = 0; j < 4; j++) {
            int idx = tid + 256 * j;
            int fl = idx >> 4;
            int o4 = idx & 15;
            int m = o4 >> 2;      // 0..3
            int k = m & 1;
            int h4 = o4 & 3;
            const float* wp = (m < 2) ? wi : wr;
            float4 v = *(const float4*)&wp[k * 4096 + (fc + fl) * 16 + h4 * 4];
            *(float4*)&ws[fl * 64 + o4 * 4] = v;
        }
        __syncthreads();
#pragma unroll 8
        for (int f = 0; f < 64; f++) {
            float4 w = *(float4*)&ws[f * 64 + co * 4];
            u64 w01 = pack2(w.x, w.y);
            u64 w23 = pack2(w.z, w.w);
#pragma unroll
            for (int i = 0; i < 8; i++) {
                float xv = xs[(rn * 8 + i) * 68 + f];
                u64 xx = pack2(xv, xv);
                acc[i][0] = ffma2(xx, w01, acc[i][0]);
                acc[i][1] = ffma2(xx, w23, acc[i][1]);
            }
        }
        __syncthreads();
    }
#pragma unroll
    for (int i = 0; i < 8; i++) {
        int node = nb + rn * 8 + i;
        if (node >= NN) continue;
        float4 v;
        unpack2(acc[i][0], v.x, v.y);
        unpack2(acc[i][1], v.z, v.w);
        if (co < 8) {
            *(float4*)&g_h1s[node * 32 + co * 4] = v;
        } else {
            *(float4*)&g_root1[node * 32 + (co - 8) * 4] = v;
        }
    }
}

// ---------------- K: scale h1s by dinv + compress to half --------------------
__global__ void k_scale() {
    int i = blockIdx.x * blockDim.x + threadIdx.x;   // over NN*8 u64 slots
    if (i >= NN * 8) return;
    int node = i >> 3;
    float dv = g_dinv[node];
    float4 v = *(float4*)&g_h1s[i * 4];
    g_h1sh[i] = pack_h4(v.x * dv, v.y * dv, v.z * dv, v.w * dv);
}

// ---------------- layer-1 aggregate + combine --------------------------------
// warp per dst node; 4 groups x 8 lanes; 64B half rows; fp32 accumulation.
__global__ void __launch_bounds__(256) k_agg1(const float* __restrict__ bias1,
                                              float* __restrict__ out_agg) {
    int node = blockIdx.x * 8 + (threadIdx.x >> 5);
    int lane = threadIdx.x & 31;
    if (node >= NN) return;
    int beg = g_off[node], end = g_off[node + 1];
    int grp = lane >> 3;       // 0..3
    int c8 = lane & 7;         // u64 slot within row (4 half-cols each)

    float4 acc = make_float4(0.f, 0.f, 0.f, 0.f);
    int t = beg + grp;
    for (; t + 12 < end; t += 16) {
        int s0 = g_csrc[t];
        int s1 = g_csrc[t + 4];
        int s2 = g_csrc[t + 8];
        int s3 = g_csrc[t + 12];
        u64 r0 = g_h1sh[s0 * 8 + c8];
        u64 r1 = g_h1sh[s1 * 8 + c8];
        u64 r2 = g_h1sh[s2 * 8 + c8];
        u64 r3 = g_h1sh[s3 * 8 + c8];
        float4 a0, a1, a2, a3;
        unpack_h4(r0, a0); unpack_h4(r1, a1);
        unpack_h4(r2, a2); unpack_h4(r3, a3);
        acc.x += (a0.x + a1.x) + (a2.x + a3.x);
        acc.y += (a0.y + a1.y) + (a2.y + a3.y);
        acc.z += (a0.z + a1.z) + (a2.z + a3.z);
        acc.w += (a0.w + a1.w) + (a2.w + a3.w);
    }
    for (; t < end; t += 4) {
        int s = g_csrc[t];
        float4 a;
        unpack_h4(g_h1sh[s * 8 + c8], a);
        acc.x += a.x; acc.y += a.y; acc.z += a.z; acc.w += a.w;
    }
    // reduce across the 4 neighbor groups (lane bits 3,4)
#pragma unroll
    for (int m = 8; m <= 16; m <<= 1) {
        acc.x += __shfl_xor_sync(0xffffffffu, acc.x, m);
        acc.y += __shfl_xor_sync(0xffffffffu, acc.y, m);
        acc.z += __shfl_xor_sync(0xffffffffu, acc.z, m);
        acc.w += __shfl_xor_sync(0xffffffffu, acc.w, m);
    }
    // lanes 0..7 hold full col sums for cols c8*4 .. c8*4+3
    int cb = c8 * 4;
    float dv = g_dinv[node];
    float4 root = *(const float4*)&g_root1[node * 32 + cb];
    float4 bv = *(const float4*)&bias1[cb];
    float4 r;
    r.x = fmaxf(dv * acc.x + root.x + bv.x, 0.f);
    r.y = fmaxf(dv * acc.y + root.y + bv.y, 0.f);
    r.z = fmaxf(dv * acc.z + root.z + bv.z, 0.f);
    r.w = fmaxf(dv * acc.w + root.w + bv.w, 0.f);
    // K-mean: col c pairs with c+16 -> lane pairs with lane^4
    float4 o;
    o.x = __shfl_xor_sync(0xffffffffu, r.x, 4);
    o.y = __shfl_xor_sync(0xffffffffu, r.y, 4);
    o.z = __shfl_xor_sync(0xffffffffu, r.z, 4);
    o.w = __shfl_xor_sync(0xffffffffu, r.w, 4);
    float4 h;
    h.x = 0.5f * (r.x + o.x);
    h.y = 0.5f * (r.y + o.y);
    h.z = 0.5f * (r.z + o.z);
    h.w = 0.5f * (r.w + o.w);
    if (lane < 4) {
        *(float4*)&out_agg[node * 16 + lane * 4] = h;   // agg_feature (fp32)
        g_hsh[node * 4 + lane] = pack_h4(h.x * dv, h.y * dv, h.z * dv, h.w * dv);
    }
}

// ---------------- layer-2 aggregate ------------------------------------------
// warp per dst node; 8 groups x 4 lanes; 32B half rows; fp32 accumulation.
__global__ void __launch_bounds__(256) k_agg2() {
    int node = blockIdx.x * 8 + (threadIdx.x >> 5);
    int lane = threadIdx.x & 31;
    if (node >= NN) return;
    int beg = g_off[node], end = g_off[node + 1];
    int grp = lane >> 2;       // 0..7
    int c4 = lane & 3;         // u64 slot within row

    float4 acc = make_float4(0.f, 0.f, 0.f, 0.f);
    int t = beg + grp;
    for (; t + 24 < end; t += 32) {
        int s0 = g_csrc[t];
        int s1 = g_csrc[t + 8];
        int s2 = g_csrc[t + 16];
        int s3 = g_csrc[t + 24];
        float4 a0, a1, a2, a3;
        unpack_h4(g_hsh[s0 * 4 + c4], a0);
        unpack_h4(g_hsh[s1 * 4 + c4], a1);
        unpack_h4(g_hsh[s2 * 4 + c4], a2);
        unpack_h4(g_hsh[s3 * 4 + c4], a3);
        acc.x += (a0.x + a1.x) + (a2.x + a3.x);
        acc.y += (a0.y + a1.y) + (a2.y + a3.y);
        acc.z += (a0.z + a1.z) + (a2.z + a3.z);
        acc.w += (a0.w + a1.w) + (a2.w + a3.w);
    }
    for (; t < end; t += 8) {
        int s = g_csrc[t];
        float4 a;
        unpack_h4(g_hsh[s * 4 + c4], a);
        acc.x += a.x; acc.y += a.y; acc.z += a.z; acc.w += a.w;
    }
#pragma unroll
    for (int m = 4; m <= 16; m <<= 1) {
        acc.x += __shfl_xor_sync(0xffffffffu, acc.x, m);
        acc.y += __shfl_xor_sync(0xffffffffu, acc.y, m);
        acc.z += __shfl_xor_sync(0xffffffffu, acc.z, m);
        acc.w += __shfl_xor_sync(0xffffffffu, acc.w, m);
    }
    if (lane < 4) {
        float dv = g_dinv[node];
        float4 v = make_float4(acc.x * dv, acc.y * dv, acc.z * dv, acc.w * dv);
        *(float4*)&g_aggh[node * 16 + lane * 4] = v;
    }
}

// ---------------- layer-2 transform + log_softmax ----------------------------
__global__ void __launch_bounds__(256) k_final(const float* __restrict__ wi2,
                                               const float* __restrict__ wr2,
                                               const float* __restrict__ b2,
                                               const float* __restrict__ hsrc,
                                               float* __restrict__ out_logits) {
    __shared__ float Wi[256], Wr[256], Ba[16];
    int t = threadIdx.x;
    // K-mean commutes with identity activation -> average weights over stacks
    Wi[t] = 0.5f * (wi2[t] + wi2[256 + t]);
    Wr[t] = 0.5f * (wr2[t] + wr2[256 + t]);
    if (t < 16) Ba[t] = 0.5f * (b2[t] + b2[16 + t]);
    __syncthreads();

    int n = blockIdx.x * 256 + t;
    if (n >= NN) return;
    float g[16], h[16];
#pragma unroll
    for (int j = 0; j < 4; j++) {
        float4 gv = *(const float4*)&g_aggh[n * 16 + j * 4];
        float4 hv = *(const float4*)&hsrc[n * 16 + j * 4];
        g[j * 4 + 0] = gv.x; g[j * 4 + 1] = gv.y; g[j * 4 + 2] = gv.z; g[j * 4 + 3] = gv.w;
        h[j * 4 + 0] = hv.x; h[j * 4 + 1] = hv.y; h[j * 4 + 2] = hv.z; h[j * 4 + 3] = hv.w;
    }
    float l[16];
    float m = -1e30f;
#pragma unroll
    for (int o = 0; o < 16; o++) {
        float a = Ba[o];
#pragma unroll
        for (int ff = 0; ff < 16; ff++)
            a += g[ff] * Wi[ff * 16 + o] + h[ff] * Wr[ff * 16 + o];
        l[o] = a;
        m = fmaxf(m, a);
    }
    float s = 0.f;
#pragma unroll
    for (int o = 0; o < 16; o++) s += expf(l[o] - m);
    float ls = logf(s);
#pragma unroll
    for (int j = 0; j < 4; j++) {
        float4 v;
        v.x = l[j * 4 + 0] - m - ls;
        v.y = l[j * 4 + 1] - m - ls;
        v.z = l[j * 4 + 2] - m - ls;
        v.w = l[j * 4 + 3] - m - ls;
        *(float4*)&out_logits[n * 16 + j * 4] = v;
    }
}

// ---------------- launch -----------------------------------------------------
extern "C" void kernel_launch(void* const* d_in, const int* in_sizes, int n_in,
                              void* d_out, int out_size) {
    const float* x   = (const float*)d_in[0];
    const int*   ei  = (const int*)d_in[1];     // int32 (JAX x64 disabled)
    const float* wi1 = (const float*)d_in[2];
    const float* wr1 = (const float*)d_in[3];
    const float* b1  = (const float*)d_in[4];
    const float* wi2 = (const float*)d_in[5];
    const float* wr2 = (const float*)d_in[6];
    const float* b2  = (const float*)d_in[7];
    float* out        = (float*)d_out;
    float* out_logits = out;            // [N, 16] log_softmax
    float* out_agg    = out + NN * 16;  // [N, 16] agg_feature

    bool dual = g_hx.ok;
    if (dual) {
        cudaEventRecord(g_hx.ev_fork, 0);
        // #1: fused CSR build (enqueued FIRST -> all 592 blocks resident)
        k_build<<<GRID_B, 256>>>(ei);
        cudaEventRecord(g_hx.ev_build, 0);
        // s2: #2 gemm1 (overlaps build), #3 scale (needs dinv from build)
        cudaStreamWaitEvent(g_hx.s2, g_hx.ev_fork, 0);
        k_gemm1<<<(NN + 127) / 128, 256, 0, g_hx.s2>>>(x, wi1, wr1);
        cudaStreamWaitEvent(g_hx.s2, g_hx.ev_build, 0);
        k_scale<<<(NN * 8 + 255) / 256, 256, 0, g_hx.s2>>>();
        cudaEventRecord(g_hx.ev_join, g_hx.s2);
        cudaStreamWaitEvent(0, g_hx.ev_join, 0);
    } else {
        k_build<<<GRID_B, 256>>>(ei);
        k_gemm1<<<(NN + 127) / 128, 256>>>(x, wi1, wr1);
        k_scale<<<(NN * 8 + 255) / 256, 256>>>();
    }

    // #4 <- ncu profiles this launch
    k_agg1<<<(NN + 7) / 8, 256>>>(b1, out_agg);
    k_agg2<<<(NN + 7) / 8, 256>>>();
    k_final<<<(NN + 255) / 256, 256>>>(wi2, wr2, b2, out_agg, out_logits);
}

// round 12
// speedup vs baseline: 1.1107x; 1.1107x over previous
#include <cuda_runtime.h>
#include <cuda_fp16.h>

#define NN  100000
#define EE  3200000
#define NB_SCAN 391   // ceil(NN/256)

typedef unsigned long long u64;
typedef unsigned int u32;

// ---------------- scratch (static device globals; zero-init at load) --------
__device__ int   g_degi[NN];        // re-zeroed by k_csr for next invocation
__device__ float g_dinv[NN];
__device__ int   g_off[NN + 1];
__device__ int   g_cur[NN];
__device__ int   g_csrc[EE];
__device__ float g_h1s[NN * 32];    // x@init_w1 (fp32, from gemm)
__device__ float g_root1[NN * 32];  // x@root_w1 (fp32)
__device__ u64   g_h1sh[NN * 8];    // half-packed dinv[n]*h1s rows (64B/row)
__device__ u64   g_hsh[NN * 4];     // half-packed dinv[n]*h rows   (32B/row)
__device__ int   g_bsum[512];

// ---------------- streams/events (created at image load, before harness) ----
struct HxStreams {
    cudaStream_t s2 = nullptr;
    cudaEvent_t ev_fork = nullptr, ev_dinv = nullptr, ev_join = nullptr;
    bool ok = false;
    HxStreams() {
        ok = (cudaStreamCreateWithFlags(&s2, cudaStreamNonBlocking) == cudaSuccess) &&
             (cudaEventCreateWithFlags(&ev_fork, cudaEventDisableTiming) == cudaSuccess) &&
             (cudaEventCreateWithFlags(&ev_dinv, cudaEventDisableTiming) == cudaSuccess) &&
             (cudaEventCreateWithFlags(&ev_join, cudaEventDisableTiming) == cudaSuccess);
    }
};
static HxStreams g_hx;

// ---------------- packed f32x2 helpers ---------------------------------------
__device__ __forceinline__ u64 ffma2(u64 a, u64 b, u64 c) {
    u64 d;
    asm("fma.rn.f32x2 %0, %1, %2, %3;" : "=l"(d) : "l"(a), "l"(b), "l"(c));
    return d;
}
__device__ __forceinline__ u64 pack2(float lo, float hi) {
    u64 r;
    asm("mov.b64 %0, {%1, %2};" : "=l"(r) : "f"(lo), "f"(hi));
    return r;
}
__device__ __forceinline__ void unpack2(u64 v, float& lo, float& hi) {
    asm("mov.b64 {%0, %1}, %2;" : "=f"(lo), "=f"(hi) : "l"(v));
}

// half helpers: u64 <-> 4 floats
__device__ __forceinline__ u64 pack_h4(float a, float b, float c, float d) {
    __half2 lo = __floats2half2_rn(a, b);
    __half2 hi = __floats2half2_rn(c, d);
    u32 ulo = *reinterpret_cast<u32*>(&lo);
    u32 uhi = *reinterpret_cast<u32*>(&hi);
    return (u64)ulo | ((u64)uhi << 32);
}
__device__ __forceinline__ void unpack_h4(u64 v, float4& f) {
    u32 ulo = (u32)v, uhi = (u32)(v >> 32);
    __half2 hlo = *reinterpret_cast<__half2*>(&ulo);
    __half2 hhi = *reinterpret_cast<__half2*>(&uhi);
    float2 a = __half22float2(hlo);
    float2 b = __half22float2(hhi);
    f.x = a.x; f.y = a.y; f.z = b.x; f.w = b.y;
}

// ---------------- K1: degree histogram (int32 dst, int4 vectorized) ---------
// assumes g_degi == 0 (load-time zero-init; re-zeroed by k_csr each call)
__global__ void k_hist(const int* __restrict__ ei) {
    int e4 = blockIdx.x * blockDim.x + threadIdx.x;
    if (e4 >= EE / 4) return;
    int4 d = *(const int4*)&ei[EE + e4 * 4];
    if ((unsigned)d.x < NN) atomicAdd(&g_degi[d.x], 1);
    if ((unsigned)d.y < NN) atomicAdd(&g_degi[d.y], 1);
    if ((unsigned)d.z < NN) atomicAdd(&g_degi[d.z], 1);
    if ((unsigned)d.w < NN) atomicAdd(&g_degi[d.w], 1);
}

// ---------------- K2: scan partials + dinv ------------------------------------
__global__ void k_scan_part() {
    __shared__ int sm[256];
    int t = threadIdx.x, b = blockIdx.x;
    int n = b * 256 + t;
    int v = (n < NN) ? g_degi[n] : 0;
    if (n < NN) g_dinv[n] = (v > 0) ? rsqrtf((float)v) : 0.0f;
    sm[t] = v;
    __syncthreads();
    for (int s = 128; s > 0; s >>= 1) {
        if (t < s) sm[t] += sm[t + s];
        __syncthreads();
    }
    if (t == 0) g_bsum[b] = sm[0];
}

// ---------------- K3: merged top-scan + output scan --------------------------
__global__ void k_scan_out2() {
    __shared__ int red[256];
    __shared__ int sm[256];
    int t = threadIdx.x, b = blockIdx.x;
    // block offset = sum of g_bsum[0..b)  (cooperative)
    int partial = 0;
    for (int j = t; j < b; j += 256) partial += g_bsum[j];
    red[t] = partial;
    __syncthreads();
    for (int s = 128; s > 0; s >>= 1) {
        if (t < s) red[t] += red[t + s];
        __syncthreads();
    }
    int boff = red[0];
    // local inclusive scan of this block's degrees
    int n = b * 256 + t;
    int v = (n < NN) ? g_degi[n] : 0;
    sm[t] = v;
    __syncthreads();
    for (int d = 1; d < 256; d <<= 1) {
        int x = (t >= d) ? sm[t - d] : 0;
        __syncthreads();
        sm[t] += x;
        __syncthreads();
    }
    int excl = sm[t] - v + boff;
    if (n < NN) {
        g_off[n] = excl;
        g_cur[n] = excl;
    }
    if (b == 0 && t == 0) g_off[NN] = EE;
}

// ---------------- K4: CSR scatter + re-zero g_degi for next call -------------
__global__ void k_csr(const int* __restrict__ ei) {
    int e4 = blockIdx.x * blockDim.x + threadIdx.x;
    if (e4 < EE / 4) {
        int4 s = *(const int4*)&ei[e4 * 4];
        int4 d = *(const int4*)&ei[EE + e4 * 4];
        if ((unsigned)d.x < NN) g_csrc[atomicAdd(&g_cur[d.x], 1)] = s.x;
        if ((unsigned)d.y < NN) g_csrc[atomicAdd(&g_cur[d.y], 1)] = s.y;
        if ((unsigned)d.z < NN) g_csrc[atomicAdd(&g_cur[d.z], 1)] = s.z;
        if ((unsigned)d.w < NN) g_csrc[atomicAdd(&g_cur[d.w], 1)] = s.w;
    }
    if (e4 < NN) g_degi[e4] = 0;   // ready for next invocation's k_hist
}

// ---------------- GEMM1 (champion variant, ~86us measured) -------------------
// tile: 128 nodes x 64 outputs, 256 threads; thread = 8 rows x 4 cols (f32x2)
__global__ void __launch_bounds__(256) k_gemm1(const float* __restrict__ x,
                                               const float* __restrict__ wi,
                                               const float* __restrict__ wr) {
    __shared__ float xs[128 * 68];
    __shared__ float ws[64 * 64];
    int tid = threadIdx.x;
    int nb = blockIdx.x * 128;
    int co = tid & 15;   // output group: cols co*4 .. co*4+3
    int rn = tid >> 4;   // row group:    rows rn*8 .. rn*8+7

    u64 acc[8][2];
#pragma unroll
    for (int i = 0; i < 8; i++) { acc[i][0] = 0ull; acc[i][1] = 0ull; }

    for (int fc = 0; fc < 256; fc += 64) {
#pragma unroll
        for (int j = 0; j < 8; j++) {
            int idx = tid + 256 * j;
            int r = idx >> 4;
            int c4 = (idx & 15) * 4;
            float4 v = make_float4(0.f, 0.f, 0.f, 0.f);
            int node = nb + r;
            if (node < NN) v = *(const float4*)&x[node * 256 + fc + c4];
            *(float4*)&xs[r * 68 + c4] = v;
        }
#pragma unroll
        for (int j = 0; j < 4; j++) {
            int idx = tid + 256 * j;
            int fl = idx >> 4;
            int o4 = idx & 15;
            int m = o4 >> 2;      // 0..3
            int k = m & 1;
            int h4 = o4 & 3;
            const float* wp = (m < 2) ? wi : wr;
            float4 v = *(const float4*)&wp[k * 4096 + (fc + fl) * 16 + h4 * 4];
            *(float4*)&ws[fl * 64 + o4 * 4] = v;
        }
        __syncthreads();
#pragma unroll 8
        for (int f = 0; f < 64; f++) {
            float4 w = *(float4*)&ws[f * 64 + co * 4];
            u64 w01 = pack2(w.x, w.y);
            u64 w23 = pack2(w.z, w.w);
#pragma unroll
            for (int i = 0; i < 8; i++) {
                float xv = xs[(rn * 8 + i) * 68 + f];
                u64 xx = pack2(xv, xv);
                acc[i][0] = ffma2(xx, w01, acc[i][0]);
                acc[i][1] = ffma2(xx, w23, acc[i][1]);
            }
        }
        __syncthreads();
    }
#pragma unroll
    for (int i = 0; i < 8; i++) {
        int node = nb + rn * 8 + i;
        if (node >= NN) continue;
        float4 v;
        unpack2(acc[i][0], v.x, v.y);
        unpack2(acc[i][1], v.z, v.w);
        if (co < 8) {
            *(float4*)&g_h1s[node * 32 + co * 4] = v;
        } else {
            *(float4*)&g_root1[node * 32 + (co - 8) * 4] = v;
        }
    }
}

// ---------------- K: scale h1s by dinv + compress to half --------------------
__global__ void k_scale() {
    int i = blockIdx.x * blockDim.x + threadIdx.x;   // over NN*8 u64 slots
    if (i >= NN * 8) return;
    int node = i >> 3;
    float dv = g_dinv[node];
    float4 v = *(float4*)&g_h1s[i * 4];
    g_h1sh[i] = pack_h4(v.x * dv, v.y * dv, v.z * dv, v.w * dv);
}

// ---------------- layer-1 aggregate + combine --------------------------------
// warp per dst node; 4 groups x 8 lanes; 64B half rows; fp32 accumulation.
__global__ void __launch_bounds__(256) k_agg1(const float* __restrict__ bias1,
                                              float* __restrict__ out_agg) {
    int node = blockIdx.x * 8 + (threadIdx.x >> 5);
    int lane = threadIdx.x & 31;
    if (node >= NN) return;
    int beg = g_off[node], end = g_off[node + 1];
    int grp = lane >> 3;       // 0..3
    int c8 = lane & 7;         // u64 slot within row (4 half-cols each)

    float4 acc = make_float4(0.f, 0.f, 0.f, 0.f);
    int t = beg + grp;
    for (; t + 12 < end; t += 16) {
        int s0 = g_csrc[t];
        int s1 = g_csrc[t + 4];
        int s2 = g_csrc[t + 8];
        int s3 = g_csrc[t + 12];
        u64 r0 = g_h1sh[s0 * 8 + c8];
        u64 r1 = g_h1sh[s1 * 8 + c8];
        u64 r2 = g_h1sh[s2 * 8 + c8];
        u64 r3 = g_h1sh[s3 * 8 + c8];
        float4 a0, a1, a2, a3;
        unpack_h4(r0, a0); unpack_h4(r1, a1);
        unpack_h4(r2, a2); unpack_h4(r3, a3);
        acc.x += (a0.x + a1.x) + (a2.x + a3.x);
        acc.y += (a0.y + a1.y) + (a2.y + a3.y);
        acc.z += (a0.z + a1.z) + (a2.z + a3.z);
        acc.w += (a0.w + a1.w) + (a2.w + a3.w);
    }
    for (; t < end; t += 4) {
        int s = g_csrc[t];
        float4 a;
        unpack_h4(g_h1sh[s * 8 + c8], a);
        acc.x += a.x; acc.y += a.y; acc.z += a.z; acc.w += a.w;
    }
    // reduce across the 4 neighbor groups (lane bits 3,4)
#pragma unroll
    for (int m = 8; m <= 16; m <<= 1) {
        acc.x += __shfl_xor_sync(0xffffffffu, acc.x, m);
        acc.y += __shfl_xor_sync(0xffffffffu, acc.y, m);
        acc.z += __shfl_xor_sync(0xffffffffu, acc.z, m);
        acc.w += __shfl_xor_sync(0xffffffffu, acc.w, m);
    }
    // lanes 0..7 hold full col sums for cols c8*4 .. c8*4+3
    int cb = c8 * 4;
    float dv = g_dinv[node];
    float4 root = *(const float4*)&g_root1[node * 32 + cb];
    float4 bv = *(const float4*)&bias1[cb];
    float4 r;
    r.x = fmaxf(dv * acc.x + root.x + bv.x, 0.f);
    r.y = fmaxf(dv * acc.y + root.y + bv.y, 0.f);
    r.z = fmaxf(dv * acc.z + root.z + bv.z, 0.f);
    r.w = fmaxf(dv * acc.w + root.w + bv.w, 0.f);
    // K-mean: col c pairs with c+16 -> lane pairs with lane^4
    float4 o;
    o.x = __shfl_xor_sync(0xffffffffu, r.x, 4);
    o.y = __shfl_xor_sync(0xffffffffu, r.y, 4);
    o.z = __shfl_xor_sync(0xffffffffu, r.z, 4);
    o.w = __shfl_xor_sync(0xffffffffu, r.w, 4);
    float4 h;
    h.x = 0.5f * (r.x + o.x);
    h.y = 0.5f * (r.y + o.y);
    h.z = 0.5f * (r.z + o.z);
    h.w = 0.5f * (r.w + o.w);
    if (lane < 4) {
        *(float4*)&out_agg[node * 16 + lane * 4] = h;   // agg_feature (fp32)
        g_hsh[node * 4 + lane] = pack_h4(h.x * dv, h.y * dv, h.z * dv, h.w * dv);
    }
}

// ---------------- layer-2 aggregate + transform + log_softmax (fused) --------
// warp per dst node; 8 groups x 4 lanes gather; then in-warp 16x16 transform.
__global__ void __launch_bounds__(256) k_agg2f(const float* __restrict__ wi2,
                                               const float* __restrict__ wr2,
                                               const float* __restrict__ b2,
                                               const float* __restrict__ hsrc,
                                               float* __restrict__ out_logits) {
    __shared__ float Wi[256], Wr[256], Ba[16];
    int tt = threadIdx.x;
    // K-mean commutes with identity activation -> average weights over stacks
    Wi[tt] = 0.5f * (wi2[tt] + wi2[256 + tt]);
    Wr[tt] = 0.5f * (wr2[tt] + wr2[256 + tt]);
    if (tt < 16) Ba[tt] = 0.5f * (b2[tt] + b2[16 + tt]);
    __syncthreads();

    int node = blockIdx.x * 8 + (tt >> 5);
    int lane = tt & 31;
    if (node >= NN) return;
    int beg = g_off[node], end = g_off[node + 1];
    int grp = lane >> 2;       // 0..7
    int c4 = lane & 3;         // u64 slot within row

    float4 acc = make_float4(0.f, 0.f, 0.f, 0.f);
    int t = beg + grp;
    for (; t + 24 < end; t += 32) {
        int s0 = g_csrc[t];
        int s1 = g_csrc[t + 8];
        int s2 = g_csrc[t + 16];
        int s3 = g_csrc[t + 24];
        float4 a0, a1, a2, a3;
        unpack_h4(g_hsh[s0 * 4 + c4], a0);
        unpack_h4(g_hsh[s1 * 4 + c4], a1);
        unpack_h4(g_hsh[s2 * 4 + c4], a2);
        unpack_h4(g_hsh[s3 * 4 + c4], a3);
        acc.x += (a0.x + a1.x) + (a2.x + a3.x);
        acc.y += (a0.y + a1.y) + (a2.y + a3.y);
        acc.z += (a0.z + a1.z) + (a2.z + a3.z);
        acc.w += (a0.w + a1.w) + (a2.w + a3.w);
    }
    for (; t < end; t += 8) {
        int s = g_csrc[t];
        float4 a;
        unpack_h4(g_hsh[s * 4 + c4], a);
        acc.x += a.x; acc.y += a.y; acc.z += a.z; acc.w += a.w;
    }
#pragma unroll
    for (int m = 4; m <= 16; m <<= 1) {
        acc.x += __shfl_xor_sync(0xffffffffu, acc.x, m);
        acc.y += __shfl_xor_sync(0xffffffffu, acc.y, m);
        acc.z += __shfl_xor_sync(0xffffffffu, acc.z, m);
        acc.w += __shfl_xor_sync(0xffffffffu, acc.w, m);
    }
    // now every lane holds col-group (lane&3) totals in acc.{x..w}
    float dv = g_dinv[node];
    // broadcast all 16 g values to every lane (width-4 shfls)
    float gg[16];
#pragma unroll
    for (int q = 0; q < 4; q++) {
        gg[q * 4 + 0] = __shfl_sync(0xffffffffu, acc.x, q, 4) * dv;
        gg[q * 4 + 1] = __shfl_sync(0xffffffffu, acc.y, q, 4) * dv;
        gg[q * 4 + 2] = __shfl_sync(0xffffffffu, acc.z, q, 4) * dv;
        gg[q * 4 + 3] = __shfl_sync(0xffffffffu, acc.w, q, 4) * dv;
    }
    // h vector (fp32, from agg1 output) — same address all lanes -> broadcast
    float hh[16];
#pragma unroll
    for (int j = 0; j < 4; j++) {
        float4 hv = *(const float4*)&hsrc[node * 16 + j * 4];
        hh[j * 4 + 0] = hv.x; hh[j * 4 + 1] = hv.y;
        hh[j * 4 + 2] = hv.z; hh[j * 4 + 3] = hv.w;
    }
    // lane o (o = lane & 15) computes logit o; lanes 16-31 duplicate
    int o = lane & 15;
    float l = Ba[o];
#pragma unroll
    for (int f = 0; f < 16; f++)
        l += gg[f] * Wi[f * 16 + o] + hh[f] * Wr[f * 16 + o];
    // softmax over the 16-lane group
    float m = l;
#pragma unroll
    for (int mm = 1; mm <= 8; mm <<= 1)
        m = fmaxf(m, __shfl_xor_sync(0xffffffffu, m, mm));
    float e = expf(l - m);
    float s = e;
#pragma unroll
    for (int mm = 1; mm <= 8; mm <<= 1)
        s += __shfl_xor_sync(0xffffffffu, s, mm);
    float res = l - m - logf(s);
    if (lane < 16) out_logits[node * 16 + o] = res;
}

// ---------------- launch -----------------------------------------------------
extern "C" void kernel_launch(void* const* d_in, const int* in_sizes, int n_in,
                              void* d_out, int out_size) {
    const float* x   = (const float*)d_in[0];
    const int*   ei  = (const int*)d_in[1];     // int32 (JAX x64 disabled)
    const float* wi1 = (const float*)d_in[2];
    const float* wr1 = (const float*)d_in[3];
    const float* b1  = (const float*)d_in[4];
    const float* wi2 = (const float*)d_in[5];
    const float* wr2 = (const float*)d_in[6];
    const float* b2  = (const float*)d_in[7];
    float* out        = (float*)d_out;
    float* out_logits = out;            // [N, 16] log_softmax
    float* out_agg    = out + NN * 16;  // [N, 16] agg_feature

    bool dual = g_hx.ok;
    if (dual) {
        cudaEventRecord(g_hx.ev_fork, 0);
        // stream 0: CSR chain
        k_hist<<<(EE / 4 + 255) / 256, 256>>>(ei);               // #1
        k_scan_part<<<NB_SCAN, 256>>>();                         // #2
        cudaEventRecord(g_hx.ev_dinv, 0);
        k_scan_out2<<<NB_SCAN, 256>>>();                         // #3
        k_csr<<<(EE / 4 + 255) / 256, 256>>>(ei);                // #4 <- profiled
        // s2: gemm (independent) then scale (needs dinv)
        cudaStreamWaitEvent(g_hx.s2, g_hx.ev_fork, 0);
        k_gemm1<<<(NN + 127) / 128, 256, 0, g_hx.s2>>>(x, wi1, wr1);   // #5
        cudaStreamWaitEvent(g_hx.s2, g_hx.ev_dinv, 0);
        k_scale<<<(NN * 8 + 255) / 256, 256, 0, g_hx.s2>>>();          // #6
        cudaEventRecord(g_hx.ev_join, g_hx.s2);
        cudaStreamWaitEvent(0, g_hx.ev_join, 0);
    } else {
        k_hist<<<(EE / 4 + 255) / 256, 256>>>(ei);
        k_scan_part<<<NB_SCAN, 256>>>();
        k_scan_out2<<<NB_SCAN, 256>>>();
        k_csr<<<(EE / 4 + 255) / 256, 256>>>(ei);
        k_gemm1<<<(NN + 127) / 128, 256>>>(x, wi1, wr1);
        k_scale<<<(NN * 8 + 255) / 256, 256>>>();
    }

    k_agg1<<<(NN + 7) / 8, 256>>>(b1, out_agg);                  // #7
    k_agg2f<<<(NN + 7) / 8, 256>>>(wi2, wr2, b2, out_agg, out_logits);  // #8
}

// round 13
// speedup vs baseline: 1.1120x; 1.0012x over previous
#include <cuda_runtime.h>
#include <cuda_fp16.h>

#define NN  100000
#define EE  3200000
#define NB_SCAN 391   // ceil(NN/256)

typedef unsigned long long u64;
typedef unsigned int u32;

// ---------------- scratch (static device globals; zero-init at load) --------
__device__ int   g_degi[NN];        // re-zeroed by k_csr for next invocation
__device__ float g_dinv[NN];
__device__ int   g_off[NN + 1];
__device__ int   g_rank[EE];        // within-dst rank of each edge (from hist)
__device__ int   g_csrc[EE];
__device__ float g_h1s[NN * 32];    // x@init_w1 (fp32, from gemm)
__device__ float g_root1[NN * 32];  // x@root_w1 (fp32)
__device__ u64   g_h1sh[NN * 8];    // half-packed dinv[n]*h1s rows (64B/row)
__device__ u64   g_hsh[NN * 4];     // half-packed dinv[n]*h rows   (32B/row)
__device__ int   g_bsum[512];

// ---------------- streams/events (created at image load, before harness) ----
struct HxStreams {
    cudaStream_t s2 = nullptr;
    cudaEvent_t ev_fork = nullptr, ev_dinv = nullptr, ev_join = nullptr;
    bool ok = false;
    HxStreams() {
        ok = (cudaStreamCreateWithFlags(&s2, cudaStreamNonBlocking) == cudaSuccess) &&
             (cudaEventCreateWithFlags(&ev_fork, cudaEventDisableTiming) == cudaSuccess) &&
             (cudaEventCreateWithFlags(&ev_dinv, cudaEventDisableTiming) == cudaSuccess) &&
             (cudaEventCreateWithFlags(&ev_join, cudaEventDisableTiming) == cudaSuccess);
    }
};
static HxStreams g_hx;

// ---------------- packed f32x2 helpers ---------------------------------------
__device__ __forceinline__ u64 ffma2(u64 a, u64 b, u64 c) {
    u64 d;
    asm("fma.rn.f32x2 %0, %1, %2, %3;" : "=l"(d) : "l"(a), "l"(b), "l"(c));
    return d;
}
__device__ __forceinline__ u64 pack2(float lo, float hi) {
    u64 r;
    asm("mov.b64 %0, {%1, %2};" : "=l"(r) : "f"(lo), "f"(hi));
    return r;
}
__device__ __forceinline__ void unpack2(u64 v, float& lo, float& hi) {
    asm("mov.b64 {%0, %1}, %2;" : "=f"(lo), "=f"(hi) : "l"(v));
}

// half helpers: u64 <-> 4 floats
__device__ __forceinline__ u64 pack_h4(float a, float b, float c, float d) {
    __half2 lo = __floats2half2_rn(a, b);
    __half2 hi = __floats2half2_rn(c, d);
    u32 ulo = *reinterpret_cast<u32*>(&lo);
    u32 uhi = *reinterpret_cast<u32*>(&hi);
    return (u64)ulo | ((u64)uhi << 32);
}
__device__ __forceinline__ void unpack_h4(u64 v, float4& f) {
    u32 ulo = (u32)v, uhi = (u32)(v >> 32);
    __half2 hlo = *reinterpret_cast<__half2*>(&ulo);
    __half2 hhi = *reinterpret_cast<__half2*>(&uhi);
    float2 a = __half22float2(hlo);
    float2 b = __half22float2(hhi);
    f.x = a.x; f.y = a.y; f.z = b.x; f.w = b.y;
}

// ---------------- K1: degree histogram + rank recording ----------------------
// assumes g_degi == 0 (load-time zero-init; re-zeroed by k_csr each call).
// The atomicAdd return value IS the edge's within-node rank -> the scatter
// pass needs no atomics at all.
__global__ void k_hist(const int* __restrict__ ei) {
    int e4 = blockIdx.x * blockDim.x + threadIdx.x;
    if (e4 >= EE / 4) return;
    int4 d = *(const int4*)&ei[EE + e4 * 4];
    int4 r;
    r.x = ((unsigned)d.x < NN) ? atomicAdd(&g_degi[d.x], 1) : 0;
    r.y = ((unsigned)d.y < NN) ? atomicAdd(&g_degi[d.y], 1) : 0;
    r.z = ((unsigned)d.z < NN) ? atomicAdd(&g_degi[d.z], 1) : 0;
    r.w = ((unsigned)d.w < NN) ? atomicAdd(&g_degi[d.w], 1) : 0;
    *(int4*)&g_rank[e4 * 4] = r;
}

// ---------------- K2: scan partials + dinv ------------------------------------
__global__ void k_scan_part() {
    __shared__ int sm[256];
    int t = threadIdx.x, b = blockIdx.x;
    int n = b * 256 + t;
    int v = (n < NN) ? g_degi[n] : 0;
    if (n < NN) g_dinv[n] = (v > 0) ? rsqrtf((float)v) : 0.0f;
    sm[t] = v;
    __syncthreads();
    for (int s = 128; s > 0; s >>= 1) {
        if (t < s) sm[t] += sm[t + s];
        __syncthreads();
    }
    if (t == 0) g_bsum[b] = sm[0];
}

// ---------------- K3: merged top-scan + output scan --------------------------
__global__ void k_scan_out2() {
    __shared__ int red[256];
    __shared__ int sm[256];
    int t = threadIdx.x, b = blockIdx.x;
    // block offset = sum of g_bsum[0..b)  (cooperative)
    int partial = 0;
    for (int j = t; j < b; j += 256) partial += g_bsum[j];
    red[t] = partial;
    __syncthreads();
    for (int s = 128; s > 0; s >>= 1) {
        if (t < s) red[t] += red[t + s];
        __syncthreads();
    }
    int boff = red[0];
    // local inclusive scan of this block's degrees
    int n = b * 256 + t;
    int v = (n < NN) ? g_degi[n] : 0;
    sm[t] = v;
    __syncthreads();
    for (int d = 1; d < 256; d <<= 1) {
        int x = (t >= d) ? sm[t - d] : 0;
        __syncthreads();
        sm[t] += x;
        __syncthreads();
    }
    int excl = sm[t] - v + boff;
    if (n < NN) g_off[n] = excl;
    if (b == 0 && t == 0) g_off[NN] = EE;
}

// ---------------- K4: CSR scatter — ATOMIC-FREE (uses recorded ranks) --------
__global__ void k_csr(const int* __restrict__ ei) {
    int e4 = blockIdx.x * blockDim.x + threadIdx.x;
    if (e4 < EE / 4) {
        int4 s = *(const int4*)&ei[e4 * 4];
        int4 d = *(const int4*)&ei[EE + e4 * 4];
        int4 r = *(const int4*)&g_rank[e4 * 4];
        if ((unsigned)d.x < NN) g_csrc[g_off[d.x] + r.x] = s.x;
        if ((unsigned)d.y < NN) g_csrc[g_off[d.y] + r.y] = s.y;
        if ((unsigned)d.z < NN) g_csrc[g_off[d.z] + r.z] = s.z;
        if ((unsigned)d.w < NN) g_csrc[g_off[d.w] + r.w] = s.w;
    }
    if (e4 < NN) g_degi[e4] = 0;   // ready for next invocation's k_hist
}

// ---------------- GEMM1 (champion variant, ~86us measured) -------------------
// tile: 128 nodes x 64 outputs, 256 threads; thread = 8 rows x 4 cols (f32x2)
__global__ void __launch_bounds__(256) k_gemm1(const float* __restrict__ x,
                                               const float* __restrict__ wi,
                                               const float* __restrict__ wr) {
    __shared__ float xs[128 * 68];
    __shared__ float ws[64 * 64];
    int tid = threadIdx.x;
    int nb = blockIdx.x * 128;
    int co = tid & 15;   // output group: cols co*4 .. co*4+3
    int rn = tid >> 4;   // row group:    rows rn*8 .. rn*8+7

    u64 acc[8][2];
#pragma unroll
    for (int i = 0; i < 8; i++) { acc[i][0] = 0ull; acc[i][1] = 0ull; }

    for (int fc = 0; fc < 256; fc += 64) {
#pragma unroll
        for (int j = 0; j < 8; j++) {
            int idx = tid + 256 * j;
            int r = idx >> 4;
            int c4 = (idx & 15) * 4;
            float4 v = make_float4(0.f, 0.f, 0.f, 0.f);
            int node = nb + r;
            if (node < NN) v = *(const float4*)&x[node * 256 + fc + c4];
            *(float4*)&xs[r * 68 + c4] = v;
        }
#pragma unroll
        for (int j = 0; j < 4; j++) {
            int idx = tid + 256 * j;
            int fl = idx >> 4;
            int o4 = idx & 15;
            int m = o4 >> 2;      // 0..3
            int k = m & 1;
            int h4 = o4 & 3;
            const float* wp = (m < 2) ? wi : wr;
            float4 v = *(const float4*)&wp[k * 4096 + (fc + fl) * 16 + h4 * 4];
            *(float4*)&ws[fl * 64 + o4 * 4] = v;
        }
        __syncthreads();
#pragma unroll 8
        for (int f = 0; f < 64; f++) {
            float4 w = *(float4*)&ws[f * 64 + co * 4];
            u64 w01 = pack2(w.x, w.y);
            u64 w23 = pack2(w.z, w.w);
#pragma unroll
            for (int i = 0; i < 8; i++) {
                float xv = xs[(rn * 8 + i) * 68 + f];
                u64 xx = pack2(xv, xv);
                acc[i][0] = ffma2(xx, w01, acc[i][0]);
                acc[i][1] = ffma2(xx, w23, acc[i][1]);
            }
        }
        __syncthreads();
    }
#pragma unroll
    for (int i = 0; i < 8; i++) {
        int node = nb + rn * 8 + i;
        if (node >= NN) continue;
        float4 v;
        unpack2(acc[i][0], v.x, v.y);
        unpack2(acc[i][1], v.z, v.w);
        if (co < 8) {
            *(float4*)&g_h1s[node * 32 + co * 4] = v;
        } else {
            *(float4*)&g_root1[node * 32 + (co - 8) * 4] = v;
        }
    }
}

// ---------------- K: scale h1s by dinv + compress to half --------------------
__global__ void k_scale() {
    int i = blockIdx.x * blockDim.x + threadIdx.x;   // over NN*8 u64 slots
    if (i >= NN * 8) return;
    int node = i >> 3;
    float dv = g_dinv[node];
    float4 v = *(float4*)&g_h1s[i * 4];
    g_h1sh[i] = pack_h4(v.x * dv, v.y * dv, v.z * dv, v.w * dv);
}

// ---------------- layer-1 aggregate + combine --------------------------------
// warp per dst node; 4 groups x 8 lanes; 64B half rows; fp32 accumulation.
__global__ void __launch_bounds__(256) k_agg1(const float* __restrict__ bias1,
                                              float* __restrict__ out_agg) {
    int node = blockIdx.x * 8 + (threadIdx.x >> 5);
    int lane = threadIdx.x & 31;
    if (node >= NN) return;
    int beg = g_off[node], end = g_off[node + 1];
    int grp = lane >> 3;       // 0..3
    int c8 = lane & 7;         // u64 slot within row (4 half-cols each)

    float4 acc = make_float4(0.f, 0.f, 0.f, 0.f);
    int t = beg + grp;
    for (; t + 12 < end; t += 16) {
        int s0 = g_csrc[t];
        int s1 = g_csrc[t + 4];
        int s2 = g_csrc[t + 8];
        int s3 = g_csrc[t + 12];
        u64 r0 = g_h1sh[s0 * 8 + c8];
        u64 r1 = g_h1sh[s1 * 8 + c8];
        u64 r2 = g_h1sh[s2 * 8 + c8];
        u64 r3 = g_h1sh[s3 * 8 + c8];
        float4 a0, a1, a2, a3;
        unpack_h4(r0, a0); unpack_h4(r1, a1);
        unpack_h4(r2, a2); unpack_h4(r3, a3);
        acc.x += (a0.x + a1.x) + (a2.x + a3.x);
        acc.y += (a0.y + a1.y) + (a2.y + a3.y);
        acc.z += (a0.z + a1.z) + (a2.z + a3.z);
        acc.w += (a0.w + a1.w) + (a2.w + a3.w);
    }
    for (; t < end; t += 4) {
        int s = g_csrc[t];
        float4 a;
        unpack_h4(g_h1sh[s * 8 + c8], a);
        acc.x += a.x; acc.y += a.y; acc.z += a.z; acc.w += a.w;
    }
    // reduce across the 4 neighbor groups (lane bits 3,4)
#pragma unroll
    for (int m = 8; m <= 16; m <<= 1) {
        acc.x += __shfl_xor_sync(0xffffffffu, acc.x, m);
        acc.y += __shfl_xor_sync(0xffffffffu, acc.y, m);
        acc.z += __shfl_xor_sync(0xffffffffu, acc.z, m);
        acc.w += __shfl_xor_sync(0xffffffffu, acc.w, m);
    }
    // lanes 0..7 hold full col sums for cols c8*4 .. c8*4+3
    int cb = c8 * 4;
    float dv = g_dinv[node];
    float4 root = *(const float4*)&g_root1[node * 32 + cb];
    float4 bv = *(const float4*)&bias1[cb];
    float4 r;
    r.x = fmaxf(dv * acc.x + root.x + bv.x, 0.f);
    r.y = fmaxf(dv * acc.y + root.y + bv.y, 0.f);
    r.z = fmaxf(dv * acc.z + root.z + bv.z, 0.f);
    r.w = fmaxf(dv * acc.w + root.w + bv.w, 0.f);
    // K-mean: col c pairs with c+16 -> lane pairs with lane^4
    float4 o;
    o.x = __shfl_xor_sync(0xffffffffu, r.x, 4);
    o.y = __shfl_xor_sync(0xffffffffu, r.y, 4);
    o.z = __shfl_xor_sync(0xffffffffu, r.z, 4);
    o.w = __shfl_xor_sync(0xffffffffu, r.w, 4);
    float4 h;
    h.x = 0.5f * (r.x + o.x);
    h.y = 0.5f * (r.y + o.y);
    h.z = 0.5f * (r.z + o.z);
    h.w = 0.5f * (r.w + o.w);
    if (lane < 4) {
        *(float4*)&out_agg[node * 16 + lane * 4] = h;   // agg_feature (fp32)
        g_hsh[node * 4 + lane] = pack_h4(h.x * dv, h.y * dv, h.z * dv, h.w * dv);
    }
}

// ---------------- layer-2 aggregate + transform + log_softmax (fused) --------
// warp per dst node; 8 groups x 4 lanes gather; then in-warp 16x16 transform.
__global__ void __launch_bounds__(256) k_agg2f(const float* __restrict__ wi2,
                                               const float* __restrict__ wr2,
                                               const float* __restrict__ b2,
                                               const float* __restrict__ hsrc,
                                               float* __restrict__ out_logits) {
    __shared__ float Wi[256], Wr[256], Ba[16];
    int tt = threadIdx.x;
    // K-mean commutes with identity activation -> average weights over stacks
    Wi[tt] = 0.5f * (wi2[tt] + wi2[256 + tt]);
    Wr[tt] = 0.5f * (wr2[tt] + wr2[256 + tt]);
    if (tt < 16) Ba[tt] = 0.5f * (b2[tt] + b2[16 + tt]);
    __syncthreads();

    int node = blockIdx.x * 8 + (tt >> 5);
    int lane = tt & 31;
    if (node >= NN) return;
    int beg = g_off[node], end = g_off[node + 1];
    int grp = lane >> 2;       // 0..7
    int c4 = lane & 3;         // u64 slot within row

    float4 acc = make_float4(0.f, 0.f, 0.f, 0.f);
    int t = beg + grp;
    for (; t + 24 < end; t += 32) {
        int s0 = g_csrc[t];
        int s1 = g_csrc[t + 8];
        int s2 = g_csrc[t + 16];
        int s3 = g_csrc[t + 24];
        float4 a0, a1, a2, a3;
        unpack_h4(g_hsh[s0 * 4 + c4], a0);
        unpack_h4(g_hsh[s1 * 4 + c4], a1);
        unpack_h4(g_hsh[s2 * 4 + c4], a2);
        unpack_h4(g_hsh[s3 * 4 + c4], a3);
        acc.x += (a0.x + a1.x) + (a2.x + a3.x);
        acc.y += (a0.y + a1.y) + (a2.y + a3.y);
        acc.z += (a0.z + a1.z) + (a2.z + a3.z);
        acc.w += (a0.w + a1.w) + (a2.w + a3.w);
    }
    for (; t < end; t += 8) {
        int s = g_csrc[t];
        float4 a;
        unpack_h4(g_hsh[s * 4 + c4], a);
        acc.x += a.x; acc.y += a.y; acc.z += a.z; acc.w += a.w;
    }
#pragma unroll
    for (int m = 4; m <= 16; m <<= 1) {
        acc.x += __shfl_xor_sync(0xffffffffu, acc.x, m);
        acc.y += __shfl_xor_sync(0xffffffffu, acc.y, m);
        acc.z += __shfl_xor_sync(0xffffffffu, acc.z, m);
        acc.w += __shfl_xor_sync(0xffffffffu, acc.w, m);
    }
    // now every lane holds col-group (lane&3) totals in acc.{x..w}
    float dv = g_dinv[node];
    // broadcast all 16 g values to every lane (width-4 shfls)
    float gg[16];
#pragma unroll
    for (int q = 0; q < 4; q++) {
        gg[q * 4 + 0] = __shfl_sync(0xffffffffu, acc.x, q, 4) * dv;
        gg[q * 4 + 1] = __shfl_sync(0xffffffffu, acc.y, q, 4) * dv;
        gg[q * 4 + 2] = __shfl_sync(0xffffffffu, acc.z, q, 4) * dv;
        gg[q * 4 + 3] = __shfl_sync(0xffffffffu, acc.w, q, 4) * dv;
    }
    // h vector (fp32, from agg1 output) — same address all lanes -> broadcast
    float hh[16];
#pragma unroll
    for (int j = 0; j < 4; j++) {
        float4 hv = *(const float4*)&hsrc[node * 16 + j * 4];
        hh[j * 4 + 0] = hv.x; hh[j * 4 + 1] = hv.y;
        hh[j * 4 + 2] = hv.z; hh[j * 4 + 3] = hv.w;
    }
    // lane o (o = lane & 15) computes logit o; lanes 16-31 duplicate
    int o = lane & 15;
    float l = Ba[o];
#pragma unroll
    for (int f = 0; f < 16; f++)
        l += gg[f] * Wi[f * 16 + o] + hh[f] * Wr[f * 16 + o];
    // softmax over the 16-lane group
    float m = l;
#pragma unroll
    for (int mm = 1; mm <= 8; mm <<= 1)
        m = fmaxf(m, __shfl_xor_sync(0xffffffffu, m, mm));
    float e = expf(l - m);
    float s = e;
#pragma unroll
    for (int mm = 1; mm <= 8; mm <<= 1)
        s += __shfl_xor_sync(0xffffffffu, s, mm);
    float res = l - m - logf(s);
    if (lane < 16) out_logits[node * 16 + o] = res;
}

// ---------------- launch -----------------------------------------------------
extern "C" void kernel_launch(void* const* d_in, const int* in_sizes, int n_in,
                              void* d_out, int out_size) {
    const float* x   = (const float*)d_in[0];
    const int*   ei  = (const int*)d_in[1];     // int32 (JAX x64 disabled)
    const float* wi1 = (const float*)d_in[2];
    const float* wr1 = (const float*)d_in[3];
    const float* b1  = (const float*)d_in[4];
    const float* wi2 = (const float*)d_in[5];
    const float* wr2 = (const float*)d_in[6];
    const float* b2  = (const float*)d_in[7];
    float* out        = (float*)d_out;
    float* out_logits = out;            // [N, 16] log_softmax
    float* out_agg    = out + NN * 16;  // [N, 16] agg_feature

    bool dual = g_hx.ok;
    if (dual) {
        cudaEventRecord(g_hx.ev_fork, 0);
        // stream 0: CSR chain (scatter pass is now atomic-free)
        k_hist<<<(EE / 4 + 255) / 256, 256>>>(ei);               // #1
        k_scan_part<<<NB_SCAN, 256>>>();                         // #2
        cudaEventRecord(g_hx.ev_dinv, 0);
        k_scan_out2<<<NB_SCAN, 256>>>();                         // #3
        k_csr<<<(EE / 4 + 255) / 256, 256>>>(ei);                // #4 <- profiled
        // s2: gemm (independent) then scale (needs dinv)
        cudaStreamWaitEvent(g_hx.s2, g_hx.ev_fork, 0);
        k_gemm1<<<(NN + 127) / 128, 256, 0, g_hx.s2>>>(x, wi1, wr1);   // #5
        cudaStreamWaitEvent(g_hx.s2, g_hx.ev_dinv, 0);
        k_scale<<<(NN * 8 + 255) / 256, 256, 0, g_hx.s2>>>();          // #6
        cudaEventRecord(g_hx.ev_join, g_hx.s2);
        cudaStreamWaitEvent(0, g_hx.ev_join, 0);
    } else {
        k_hist<<<(EE / 4 + 255) / 256, 256>>>(ei);
        k_scan_part<<<NB_SCAN, 256>>>();
        k_scan_out2<<<NB_SCAN, 256>>>();
        k_csr<<<(EE / 4 + 255) / 256, 256>>>(ei);
        k_gemm1<<<(NN + 127) / 128, 256>>>(x, wi1, wr1);
        k_scale<<<(NN * 8 + 255) / 256, 256>>>();
    }

    k_agg1<<<(NN + 7) / 8, 256>>>(b1, out_agg);                  // #7
    k_agg2f<<<(NN + 7) / 8, 256>>>(wi2, wr2, b2, out_agg, out_logits);  // #8
}

// round 14
// speedup vs baseline: 1.1814x; 1.0625x over previous
#include <cuda_runtime.h>

#define NN  100000
#define EE  3200000
#define NB_SCAN 391   // ceil(NN/256)

typedef unsigned long long u64;

// ---------------- scratch (static device globals) ---------------------------
__device__ int   g_degi[NN];
__device__ float g_dinv[NN];
__device__ int   g_off[NN + 1];
__device__ int   g_rank[EE];        // within-dst rank of each edge (from hist)
__device__ int   g_csrc[EE];
__device__ float g_h1s[NN * 32];    // x@init_w1; after k_scale: dinv[n]*that
__device__ float g_root1[NN * 32];  // x[n] @ root_w1 (raw)
__device__ float g_hs[NN * 16];     // dinv[n] * h[n]
__device__ float g_aggh[NN * 16];   // dinv[d] * sum_src hs[src]
__device__ int   g_bsum[512];
__device__ int   g_boff[512];

// ---------------- streams/events (created at image load, before harness) ----
struct HxStreams {
    cudaStream_t s2 = nullptr;
    cudaEvent_t ev_fork = nullptr, ev_dinv = nullptr, ev_join = nullptr;
    bool ok = false;
    HxStreams() {
        ok = (cudaStreamCreateWithFlags(&s2, cudaStreamNonBlocking) == cudaSuccess) &&
             (cudaEventCreateWithFlags(&ev_fork, cudaEventDisableTiming) == cudaSuccess) &&
             (cudaEventCreateWithFlags(&ev_dinv, cudaEventDisableTiming) == cudaSuccess) &&
             (cudaEventCreateWithFlags(&ev_join, cudaEventDisableTiming) == cudaSuccess);
    }
};
static HxStreams g_hx;

// ---------------- packed f32x2 helpers ---------------------------------------
__device__ __forceinline__ u64 ffma2(u64 a, u64 b, u64 c) {
    u64 d;
    asm("fma.rn.f32x2 %0, %1, %2, %3;" : "=l"(d) : "l"(a), "l"(b), "l"(c));
    return d;
}
__device__ __forceinline__ u64 pack2(float lo, float hi) {
    u64 r;
    asm("mov.b64 %0, {%1, %2};" : "=l"(r) : "f"(lo), "f"(hi));
    return r;
}
__device__ __forceinline__ void unpack2(u64 v, float& lo, float& hi) {
    asm("mov.b64 {%0, %1}, %2;" : "=f"(lo), "=f"(hi) : "l"(v));
}

// ---------------- K: zero degree histogram -----------------------------------
__global__ void k_zero() {
    int i = blockIdx.x * blockDim.x + threadIdx.x;
    if (i < NN) g_degi[i] = 0;
}

// ---------------- K: degree histogram + rank recording -----------------------
// atomicAdd return value IS the edge's within-node arrival rank -> the
// scatter pass needs no atomics.
__global__ void k_hist(const int* __restrict__ ei) {
    int e4 = blockIdx.x * blockDim.x + threadIdx.x;
    if (e4 >= EE / 4) return;
    int4 d = *(const int4*)&ei[EE + e4 * 4];
    int4 r;
    r.x = ((unsigned)d.x < NN) ? atomicAdd(&g_degi[d.x], 1) : 0;
    r.y = ((unsigned)d.y < NN) ? atomicAdd(&g_degi[d.y], 1) : 0;
    r.z = ((unsigned)d.z < NN) ? atomicAdd(&g_degi[d.z], 1) : 0;
    r.w = ((unsigned)d.w < NN) ? atomicAdd(&g_degi[d.w], 1) : 0;
    *(int4*)&g_rank[e4 * 4] = r;
}

// ---------------- scan partials + dinv ---------------------------------------
__global__ void k_scan_part() {
    __shared__ int sm[256];
    int t = threadIdx.x, b = blockIdx.x;
    int n = b * 256 + t;
    int v = (n < NN) ? g_degi[n] : 0;
    if (n < NN) g_dinv[n] = (v > 0) ? rsqrtf((float)v) : 0.0f;
    sm[t] = v;
    __syncthreads();
    for (int s = 128; s > 0; s >>= 1) {
        if (t < s) sm[t] += sm[t + s];
        __syncthreads();
    }
    if (t == 0) g_bsum[b] = sm[0];
}

__global__ void k_scan_top() {
    __shared__ int sm[512];
    int t = threadIdx.x;
    int v = (t < NB_SCAN) ? g_bsum[t] : 0;
    sm[t] = v;
    __syncthreads();
    for (int d = 1; d < 512; d <<= 1) {
        int x = (t >= d) ? sm[t - d] : 0;
        __syncthreads();
        sm[t] += x;
        __syncthreads();
    }
    if (t < NB_SCAN) g_boff[t] = sm[t] - v;  // exclusive
}

__global__ void k_scan_out() {
    __shared__ int sm[256];
    int t = threadIdx.x, b = blockIdx.x;
    int n = b * 256 + t;
    int v = (n < NN) ? g_degi[n] : 0;
    sm[t] = v;
    __syncthreads();
    for (int d = 1; d < 256; d <<= 1) {
        int x = (t >= d) ? sm[t - d] : 0;
        __syncthreads();
        sm[t] += x;
        __syncthreads();
    }
    int excl = sm[t] - v + g_boff[b];
    if (n < NN) g_off[n] = excl;
    if (b == 0 && t == 0) g_off[NN] = EE;
}

// ---------------- CSR scatter — ATOMIC-FREE (uses recorded ranks) ------------
__global__ void k_csr(const int* __restrict__ ei) {
    int e4 = blockIdx.x * blockDim.x + threadIdx.x;
    if (e4 >= EE / 4) return;
    int4 s = *(const int4*)&ei[e4 * 4];
    int4 d = *(const int4*)&ei[EE + e4 * 4];
    int4 r = *(const int4*)&g_rank[e4 * 4];
    if ((unsigned)d.x < NN) g_csrc[g_off[d.x] + r.x] = s.x;
    if ((unsigned)d.y < NN) g_csrc[g_off[d.y] + r.y] = s.y;
    if ((unsigned)d.z < NN) g_csrc[g_off[d.z] + r.z] = s.z;
    if ((unsigned)d.w < NN) g_csrc[g_off[d.w] + r.w] = s.w;
}

// ---------------- GEMM1 (champion variant, ~86us measured) -------------------
// tile: 128 nodes x 64 outputs, 256 threads; thread = 8 rows x 4 cols (f32x2)
__global__ void __launch_bounds__(256) k_gemm1(const float* __restrict__ x,
                                               const float* __restrict__ wi,
                                               const float* __restrict__ wr) {
    __shared__ float xs[128 * 68];
    __shared__ float ws[64 * 64];
    int tid = threadIdx.x;
    int nb = blockIdx.x * 128;
    int co = tid & 15;   // output group: cols co*4 .. co*4+3
    int rn = tid >> 4;   // row group:    rows rn*8 .. rn*8+7

    u64 acc[8][2];
#pragma unroll
    for (int i = 0; i < 8; i++) { acc[i][0] = 0ull; acc[i][1] = 0ull; }

    for (int fc = 0; fc < 256; fc += 64) {
        // stage x tile [128 rows x 64 features], 8 float4/thread
#pragma unroll
        for (int j = 0; j < 8; j++) {
            int idx = tid + 256 * j;
            int r = idx >> 4;
            int c4 = (idx & 15) * 4;
            float4 v = make_float4(0.f, 0.f, 0.f, 0.f);
            int node = nb + r;
            if (node < NN) v = *(const float4*)&x[node * 256 + fc + c4];
            *(float4*)&xs[r * 68 + c4] = v;
        }
        // stage W tile [64 f x 64 outputs], 4 float4/thread
        // o layout: [wi k0 h0..15 | wi k1 h0..15 | wr k0 h0..15 | wr k1 h0..15]
#pragma unroll
        for (int j = 0; j < 4; j++) {
            int idx = tid + 256 * j;
            int fl = idx >> 4;
            int o4 = idx & 15;
            int m = o4 >> 2;      // 0..3
            int k = m & 1;
            int h4 = o4 & 3;
            const float* wp = (m < 2) ? wi : wr;
            float4 v = *(const float4*)&wp[k * 4096 + (fc + fl) * 16 + h4 * 4];
            *(float4*)&ws[fl * 64 + o4 * 4] = v;
        }
        __syncthreads();
#pragma unroll 8
        for (int f = 0; f < 64; f++) {
            float4 w = *(float4*)&ws[f * 64 + co * 4];
            u64 w01 = pack2(w.x, w.y);
            u64 w23 = pack2(w.z, w.w);
#pragma unroll
            for (int i = 0; i < 8; i++) {
                float xv = xs[(rn * 8 + i) * 68 + f];
                u64 xx = pack2(xv, xv);
                acc[i][0] = ffma2(xx, w01, acc[i][0]);
                acc[i][1] = ffma2(xx, w23, acc[i][1]);
            }
        }
        __syncthreads();
    }
    // epilogue (raw outputs; dinv applied later by k_scale)
#pragma unroll
    for (int i = 0; i < 8; i++) {
        int node = nb + rn * 8 + i;
        if (node >= NN) continue;
        float4 v;
        unpack2(acc[i][0], v.x, v.y);
        unpack2(acc[i][1], v.z, v.w);
        if (co < 8) {
            *(float4*)&g_h1s[node * 32 + co * 4] = v;
        } else {
            *(float4*)&g_root1[node * 32 + (co - 8) * 4] = v;
        }
    }
}

// ---------------- K: scale h1s rows by dinv (streaming, ~4us) ---------------
__global__ void k_scale() {
    int i = blockIdx.x * blockDim.x + threadIdx.x;   // over NN*8 float4s
    if (i >= NN * 8) return;
    int node = i >> 3;
    float dv = g_dinv[node];
    float4 v = *(float4*)&g_h1s[i * 4];
    v.x *= dv; v.y *= dv; v.z *= dv; v.w *= dv;
    *(float4*)&g_h1s[i * 4] = v;
}

// ---------------- layer-1 aggregate + combine --------------------------------
// warp per dst node; 4 groups x 8 lanes; group g handles neighbors
// beg+g, beg+g+4, ... (stride 4). No shfl: all 8 lanes of a group load the
// same g_csrc entry (hardware broadcast). Unroll x4 -> ~8 loads in flight.
__global__ void __launch_bounds__(256) k_agg1(const float* __restrict__ bias1,
                                              float* __restrict__ out_agg) {
    int node = blockIdx.x * 8 + (threadIdx.x >> 5);
    int lane = threadIdx.x & 31;
    if (node >= NN) return;
    int beg = g_off[node], end = g_off[node + 1];
    int grp = lane >> 3;       // 0..3
    int cb = (lane & 7) * 4;   // column base 0..28

    float4 acc = make_float4(0.f, 0.f, 0.f, 0.f);
    int t = beg + grp;
    for (; t + 12 < end; t += 16) {
        int s0 = g_csrc[t];
        int s1 = g_csrc[t + 4];
        int s2 = g_csrc[t + 8];
        int s3 = g_csrc[t + 12];
        float4 a0 = *(const float4*)&g_h1s[s0 * 32 + cb];
        float4 a1 = *(const float4*)&g_h1s[s1 * 32 + cb];
        float4 a2 = *(const float4*)&g_h1s[s2 * 32 + cb];
        float4 a3 = *(const float4*)&g_h1s[s3 * 32 + cb];
        acc.x += (a0.x + a1.x) + (a2.x + a3.x);
        acc.y += (a0.y + a1.y) + (a2.y + a3.y);
        acc.z += (a0.z + a1.z) + (a2.z + a3.z);
        acc.w += (a0.w + a1.w) + (a2.w + a3.w);
    }
    for (; t < end; t += 4) {
        int s = g_csrc[t];
        float4 a = *(const float4*)&g_h1s[s * 32 + cb];
        acc.x += a.x; acc.y += a.y; acc.z += a.z; acc.w += a.w;
    }
    // reduce across the 4 neighbor groups (lane bits 3,4)
#pragma unroll
    for (int m = 8; m <= 16; m <<= 1) {
        acc.x += __shfl_xor_sync(0xffffffffu, acc.x, m);
        acc.y += __shfl_xor_sync(0xffffffffu, acc.y, m);
        acc.z += __shfl_xor_sync(0xffffffffu, acc.z, m);
        acc.w += __shfl_xor_sync(0xffffffffu, acc.w, m);
    }
    // lanes 0..7 hold full col sums for cols cb..cb+3
    float dv = g_dinv[node];
    float4 root = *(const float4*)&g_root1[node * 32 + cb];
    float4 bv = *(const float4*)&bias1[cb];
    float4 r;
    r.x = fmaxf(dv * acc.x + root.x + bv.x, 0.f);
    r.y = fmaxf(dv * acc.y + root.y + bv.y, 0.f);
    r.z = fmaxf(dv * acc.z + root.z + bv.z, 0.f);
    r.w = fmaxf(dv * acc.w + root.w + bv.w, 0.f);
    // K-mean: col c pairs with c+16 -> lane pairs with lane^4
    float4 o;
    o.x = __shfl_xor_sync(0xffffffffu, r.x, 4);
    o.y = __shfl_xor_sync(0xffffffffu, r.y, 4);
    o.z = __shfl_xor_sync(0xffffffffu, r.z, 4);
    o.w = __shfl_xor_sync(0xffffffffu, r.w, 4);
    float4 h;
    h.x = 0.5f * (r.x + o.x);
    h.y = 0.5f * (r.y + o.y);
    h.z = 0.5f * (r.z + o.z);
    h.w = 0.5f * (r.w + o.w);
    if (lane < 4) {
        *(float4*)&out_agg[node * 16 + lane * 4] = h;   // agg_feature output
        float4 hs = make_float4(h.x * dv, h.y * dv, h.z * dv, h.w * dv);
        *(float4*)&g_hs[node * 16 + lane * 4] = hs;
    }
}

// ---------------- layer-2 aggregate ------------------------------------------
// warp per dst node; 8 groups x 4 lanes; group g: neighbors beg+g, +8, ...
__global__ void __launch_bounds__(256) k_agg2() {
    int node = blockIdx.x * 8 + (threadIdx.x >> 5);
    int lane = threadIdx.x & 31;
    if (node >= NN) return;
    int beg = g_off[node], end = g_off[node + 1];
    int grp = lane >> 2;       // 0..7
    int cb = (lane & 3) * 4;   // column base 0..12

    float4 acc = make_float4(0.f, 0.f, 0.f, 0.f);
    int t = beg + grp;
    for (; t + 24 < end; t += 32) {
        int s0 = g_csrc[t];
        int s1 = g_csrc[t + 8];
        int s2 = g_csrc[t + 16];
        int s3 = g_csrc[t + 24];
        float4 a0 = *(const float4*)&g_hs[s0 * 16 + cb];
        float4 a1 = *(const float4*)&g_hs[s1 * 16 + cb];
        float4 a2 = *(const float4*)&g_hs[s2 * 16 + cb];
        float4 a3 = *(const float4*)&g_hs[s3 * 16 + cb];
        acc.x += (a0.x + a1.x) + (a2.x + a3.x);
        acc.y += (a0.y + a1.y) + (a2.y + a3.y);
        acc.z += (a0.z + a1.z) + (a2.z + a3.z);
        acc.w += (a0.w + a1.w) + (a2.w + a3.w);
    }
    for (; t < end; t += 8) {
        int s = g_csrc[t];
        float4 a = *(const float4*)&g_hs[s * 16 + cb];
        acc.x += a.x; acc.y += a.y; acc.z += a.z; acc.w += a.w;
    }
#pragma unroll
    for (int m = 4; m <= 16; m <<= 1) {
        acc.x += __shfl_xor_sync(0xffffffffu, acc.x, m);
        acc.y += __shfl_xor_sync(0xffffffffu, acc.y, m);
        acc.z += __shfl_xor_sync(0xffffffffu, acc.z, m);
        acc.w += __shfl_xor_sync(0xffffffffu, acc.w, m);
    }
    if (lane < 4) {
        float dv = g_dinv[node];
        float4 v = make_float4(acc.x * dv, acc.y * dv, acc.z * dv, acc.w * dv);
        *(float4*)&g_aggh[node * 16 + lane * 4] = v;
    }
}

// ---------------- layer-2 transform + log_softmax ----------------------------
__global__ void __launch_bounds__(256) k_final(const float* __restrict__ wi2,
                                               const float* __restrict__ wr2,
                                               const float* __restrict__ b2,
                                               const float* __restrict__ hsrc,
                                               float* __restrict__ out_logits) {
    __shared__ float Wi[256], Wr[256], Ba[16];
    int t = threadIdx.x;
    // K-mean commutes with identity activation -> average weights over stacks
    Wi[t] = 0.5f * (wi2[t] + wi2[256 + t]);
    Wr[t] = 0.5f * (wr2[t] + wr2[256 + t]);
    if (t < 16) Ba[t] = 0.5f * (b2[t] + b2[16 + t]);
    __syncthreads();

    int n = blockIdx.x * 256 + t;
    if (n >= NN) return;
    float g[16], h[16];
#pragma unroll
    for (int j = 0; j < 4; j++) {
        float4 gv = *(const float4*)&g_aggh[n * 16 + j * 4];
        float4 hv = *(const float4*)&hsrc[n * 16 + j * 4];
        g[j * 4 + 0] = gv.x; g[j * 4 + 1] = gv.y; g[j * 4 + 2] = gv.z; g[j * 4 + 3] = gv.w;
        h[j * 4 + 0] = hv.x; h[j * 4 + 1] = hv.y; h[j * 4 + 2] = hv.z; h[j * 4 + 3] = hv.w;
    }
    float l[16];
    float m = -1e30f;
#pragma unroll
    for (int o = 0; o < 16; o++) {
        float a = Ba[o];
#pragma unroll
        for (int ff = 0; ff < 16; ff++)
            a += g[ff] * Wi[ff * 16 + o] + h[ff] * Wr[ff * 16 + o];
        l[o] = a;
        m = fmaxf(m, a);
    }
    float s = 0.f;
#pragma unroll
    for (int o = 0; o < 16; o++) s += expf(l[o] - m);
    float ls = logf(s);
#pragma unroll
    for (int j = 0; j < 4; j++) {
        float4 v;
        v.x = l[j * 4 + 0] - m - ls;
        v.y = l[j * 4 + 1] - m - ls;
        v.z = l[j * 4 + 2] - m - ls;
        v.w = l[j * 4 + 3] - m - ls;
        *(float4*)&out_logits[n * 16 + j * 4] = v;
    }
}

// ---------------- launch -----------------------------------------------------
extern "C" void kernel_launch(void* const* d_in, const int* in_sizes, int n_in,
                              void* d_out, int out_size) {
    const float* x   = (const float*)d_in[0];
    const int*   ei  = (const int*)d_in[1];     // int32 (JAX x64 disabled)
    const float* wi1 = (const float*)d_in[2];
    const float* wr1 = (const float*)d_in[3];
    const float* b1  = (const float*)d_in[4];
    const float* wi2 = (const float*)d_in[5];
    const float* wr2 = (const float*)d_in[6];
    const float* b2  = (const float*)d_in[7];
    float* out        = (float*)d_out;
    float* out_logits = out;            // [N, 16] log_softmax
    float* out_agg    = out + NN * 16;  // [N, 16] agg_feature

    bool dual = g_hx.ok;
    if (dual) cudaEventRecord(g_hx.ev_fork, 0);   // fork point

    // main stream: CSR build chain (R9 order; gemm enqueued early on s2)
    k_zero<<<(NN + 255) / 256, 256>>>();
    k_hist<<<(EE / 4 + 255) / 256, 256>>>(ei);
    k_scan_part<<<NB_SCAN, 256>>>();
    if (dual) cudaEventRecord(g_hx.ev_dinv, 0);   // dinv ready

    // s2: gemm1 (overlaps CSR chain), then dinv-scale of h1s
    if (dual) {
        cudaStreamWaitEvent(g_hx.s2, g_hx.ev_fork, 0);
        k_gemm1<<<(NN + 127) / 128, 256, 0, g_hx.s2>>>(x, wi1, wr1);  // 4th launch
        cudaStreamWaitEvent(g_hx.s2, g_hx.ev_dinv, 0);
        k_scale<<<(NN * 8 + 255) / 256, 256, 0, g_hx.s2>>>();
        cudaEventRecord(g_hx.ev_join, g_hx.s2);
    } else {
        k_gemm1<<<(NN + 127) / 128, 256>>>(x, wi1, wr1);
    }

    k_scan_top<<<1, 512>>>();
    k_scan_out<<<NB_SCAN, 256>>>();
    k_csr<<<(EE / 4 + 255) / 256, 256>>>(ei);

    if (dual) {
        cudaStreamWaitEvent(0, g_hx.ev_join, 0);  // join before agg1
    } else {
        k_scale<<<(NN * 8 + 255) / 256, 256>>>();
    }

    k_agg1<<<(NN + 7) / 8, 256>>>(b1, out_agg);
    k_agg2<<<(NN + 7) / 8, 256>>>();
    k_final<<<(NN + 255) / 256, 256>>>(wi2, wr2, b2, out_agg, out_logits);
}

// round 16
// speedup vs baseline: 1.2230x; 1.0352x over previous
#include <cuda_runtime.h>
#include <mma.h>

#define NN  100000
#define EE  3200000
#define NB_SCAN 391   // ceil(NN/256)

typedef unsigned long long u64;
using namespace nvcuda;

// ---------------- scratch (static device globals) ---------------------------
__device__ int   g_degi[NN];
__device__ float g_dinv[NN];
__device__ int   g_off[NN + 1];
__device__ int   g_rank[EE];        // within-dst rank of each edge (from hist)
__device__ int   g_csrc[EE];
__device__ float g_wtf[4][4096];    // tf32-rounded weights: [wiK0|wiK1|wrK0|wrK1], 256x16 ldm16
__device__ float g_h1s[NN * 32];    // x@init_w1; after k_scale: dinv[n]*that
__device__ float g_root1[NN * 32];  // x[n] @ root_w1 (raw)
__device__ float g_hs[NN * 16];     // dinv[n] * h[n]
__device__ float g_aggh[NN * 16];   // dinv[d] * sum_src hs[src]
__device__ int   g_bsum[512];
__device__ int   g_boff[512];

// ---------------- streams/events (created at image load, before harness) ----
struct HxStreams {
    cudaStream_t s2 = nullptr;
    cudaEvent_t ev_fork = nullptr, ev_dinv = nullptr, ev_join = nullptr;
    bool ok = false;
    HxStreams() {
        ok = (cudaStreamCreateWithFlags(&s2, cudaStreamNonBlocking) == cudaSuccess) &&
             (cudaEventCreateWithFlags(&ev_fork, cudaEventDisableTiming) == cudaSuccess) &&
             (cudaEventCreateWithFlags(&ev_dinv, cudaEventDisableTiming) == cudaSuccess) &&
             (cudaEventCreateWithFlags(&ev_join, cudaEventDisableTiming) == cudaSuccess);
    }
};
static HxStreams g_hx;

// ---------------- K: zero degree histogram -----------------------------------
__global__ void k_zero() {
    int i = blockIdx.x * blockDim.x + threadIdx.x;
    if (i < NN) g_degi[i] = 0;
}

// ---------------- K: degree histogram + rank recording -----------------------
__global__ void k_hist(const int* __restrict__ ei) {
    int e4 = blockIdx.x * blockDim.x + threadIdx.x;
    if (e4 >= EE / 4) return;
    int4 d = *(const int4*)&ei[EE + e4 * 4];
    int4 r;
    r.x = ((unsigned)d.x < NN) ? atomicAdd(&g_degi[d.x], 1) : 0;
    r.y = ((unsigned)d.y < NN) ? atomicAdd(&g_degi[d.y], 1) : 0;
    r.z = ((unsigned)d.z < NN) ? atomicAdd(&g_degi[d.z], 1) : 0;
    r.w = ((unsigned)d.w < NN) ? atomicAdd(&g_degi[d.w], 1) : 0;
    *(int4*)&g_rank[e4 * 4] = r;
}

// ---------------- scan partials + dinv ---------------------------------------
__global__ void k_scan_part() {
    __shared__ int sm[256];
    int t = threadIdx.x, b = blockIdx.x;
    int n = b * 256 + t;
    int v = (n < NN) ? g_degi[n] : 0;
    if (n < NN) g_dinv[n] = (v > 0) ? rsqrtf((float)v) : 0.0f;
    sm[t] = v;
    __syncthreads();
    for (int s = 128; s > 0; s >>= 1) {
        if (t < s) sm[t] += sm[t + s];
        __syncthreads();
    }
    if (t == 0) g_bsum[b] = sm[0];
}

__global__ void k_scan_top() {
    __shared__ int sm[512];
    int t = threadIdx.x;
    int v = (t < NB_SCAN) ? g_bsum[t] : 0;
    sm[t] = v;
    __syncthreads();
    for (int d = 1; d < 512; d <<= 1) {
        int x = (t >= d) ? sm[t - d] : 0;
        __syncthreads();
        sm[t] += x;
        __syncthreads();
    }
    if (t < NB_SCAN) g_boff[t] = sm[t] - v;  // exclusive
}

__global__ void k_scan_out() {
    __shared__ int sm[256];
    int t = threadIdx.x, b = blockIdx.x;
    int n = b * 256 + t;
    int v = (n < NN) ? g_degi[n] : 0;
    sm[t] = v;
    __syncthreads();
    for (int d = 1; d < 256; d <<= 1) {
        int x = (t >= d) ? sm[t - d] : 0;
        __syncthreads();
        sm[t] += x;
        __syncthreads();
    }
    int excl = sm[t] - v + g_boff[b];
    if (n < NN) g_off[n] = excl;
    if (b == 0 && t == 0) g_off[NN] = EE;
}

// ---------------- CSR scatter — ATOMIC-FREE (uses recorded ranks) ------------
__global__ void k_csr(const int* __restrict__ ei) {
    int e4 = blockIdx.x * blockDim.x + threadIdx.x;
    if (e4 >= EE / 4) return;
    int4 s = *(const int4*)&ei[e4 * 4];
    int4 d = *(const int4*)&ei[EE + e4 * 4];
    int4 r = *(const int4*)&g_rank[e4 * 4];
    if ((unsigned)d.x < NN) g_csrc[g_off[d.x] + r.x] = s.x;
    if ((unsigned)d.y < NN) g_csrc[g_off[d.y] + r.y] = s.y;
    if ((unsigned)d.z < NN) g_csrc[g_off[d.z] + r.z] = s.z;
    if ((unsigned)d.w < NN) g_csrc[g_off[d.w] + r.w] = s.w;
}

// ---------------- K: weight prep — tf32-round into [4][256x16] tables --------
__global__ void k_wprep(const float* __restrict__ wi, const float* __restrict__ wr) {
    int i = blockIdx.x * blockDim.x + threadIdx.x;   // 0..16383
    if (i >= 16384) return;
    int g = i >> 12;         // 0..3
    int r = i & 4095;
    float v = (g < 2) ? wi[g * 4096 + r] : wr[(g - 2) * 4096 + r];
    g_wtf[g][r] = wmma::__float_to_tf32(v);
}

// ---------------- GEMM1 via tf32 tensor cores (WMMA m16n16k8) ----------------
// warp = one 16-row strip of x; 4 output col-groups = the 4 weight matrices.
__global__ void __launch_bounds__(256) k_gemm1_tc(const float* __restrict__ x) {
    int warp_id = blockIdx.x * 8 + (threadIdx.x >> 5);
    int row = warp_id * 16;
    if (row >= NN) return;   // NN % 16 == 0: warps are fully in or out

    wmma::fragment<wmma::accumulator, 16, 16, 8, float> c[4];
#pragma unroll
    for (int g = 0; g < 4; g++) wmma::fill_fragment(c[g], 0.0f);

    wmma::fragment<wmma::matrix_a, 16, 16, 8, wmma::precision::tf32, wmma::row_major> a;
    wmma::fragment<wmma::matrix_b, 16, 16, 8, wmma::precision::tf32, wmma::row_major> b;

    for (int k0 = 0; k0 < 256; k0 += 8) {
        wmma::load_matrix_sync(a, x + row * 256 + k0, 256);
#pragma unroll
        for (int i = 0; i < a.num_elements; i++)
            a.x[i] = wmma::__float_to_tf32(a.x[i]);
#pragma unroll
        for (int g = 0; g < 4; g++) {
            wmma::load_matrix_sync(b, &g_wtf[g][k0 * 16], 16);
            wmma::mma_sync(c[g], a, b, c[g]);
        }
    }
    wmma::store_matrix_sync(&g_h1s[row * 32], c[0], 32, wmma::mem_row_major);
    wmma::store_matrix_sync(&g_h1s[row * 32 + 16], c[1], 32, wmma::mem_row_major);
    wmma::store_matrix_sync(&g_root1[row * 32], c[2], 32, wmma::mem_row_major);
    wmma::store_matrix_sync(&g_root1[row * 32 + 16], c[3], 32, wmma::mem_row_major);
}

// ---------------- K: scale h1s rows by dinv (streaming) ----------------------
__global__ void k_scale() {
    int i = blockIdx.x * blockDim.x + threadIdx.x;   // over NN*8 float4s
    if (i >= NN * 8) return;
    int node = i >> 3;
    float dv = g_dinv[node];
    float4 v = *(float4*)&g_h1s[i * 4];
    v.x *= dv; v.y *= dv; v.z *= dv; v.w *= dv;
    *(float4*)&g_h1s[i * 4] = v;
}

// ---------------- layer-1 aggregate + combine --------------------------------
__global__ void __launch_bounds__(256) k_agg1(const float* __restrict__ bias1,
                                              float* __restrict__ out_agg) {
    int node = blockIdx.x * 8 + (threadIdx.x >> 5);
    int lane = threadIdx.x & 31;
    if (node >= NN) return;
    int beg = g_off[node], end = g_off[node + 1];
    int grp = lane >> 3;       // 0..3
    int cb = (lane & 7) * 4;   // column base 0..28

    float4 acc = make_float4(0.f, 0.f, 0.f, 0.f);
    int t = beg + grp;
    for (; t + 12 < end; t += 16) {
        int s0 = g_csrc[t];
        int s1 = g_csrc[t + 4];
        int s2 = g_csrc[t + 8];
        int s3 = g_csrc[t + 12];
        float4 a0 = *(const float4*)&g_h1s[s0 * 32 + cb];
        float4 a1 = *(const float4*)&g_h1s[s1 * 32 + cb];
        float4 a2 = *(const float4*)&g_h1s[s2 * 32 + cb];
        float4 a3 = *(const float4*)&g_h1s[s3 * 32 + cb];
        acc.x += (a0.x + a1.x) + (a2.x + a3.x);
        acc.y += (a0.y + a1.y) + (a2.y + a3.y);
        acc.z += (a0.z + a1.z) + (a2.z + a3.z);
        acc.w += (a0.w + a1.w) + (a2.w + a3.w);
    }
    for (; t < end; t += 4) {
        int s = g_csrc[t];
        float4 a = *(const float4*)&g_h1s[s * 32 + cb];
        acc.x += a.x; acc.y += a.y; acc.z += a.z; acc.w += a.w;
    }
#pragma unroll
    for (int m = 8; m <= 16; m <<= 1) {
        acc.x += __shfl_xor_sync(0xffffffffu, acc.x, m);
        acc.y += __shfl_xor_sync(0xffffffffu, acc.y, m);
        acc.z += __shfl_xor_sync(0xffffffffu, acc.z, m);
        acc.w += __shfl_xor_sync(0xffffffffu, acc.w, m);
    }
    float dv = g_dinv[node];
    float4 root = *(const float4*)&g_root1[node * 32 + cb];
    float4 bv = *(const float4*)&bias1[cb];
    float4 r;
    r.x = fmaxf(dv * acc.x + root.x + bv.x, 0.f);
    r.y = fmaxf(dv * acc.y + root.y + bv.y, 0.f);
    r.z = fmaxf(dv * acc.z + root.z + bv.z, 0.f);
    r.w = fmaxf(dv * acc.w + root.w + bv.w, 0.f);
    // K-mean: col c pairs with c+16 -> lane pairs with lane^4
    float4 o;
    o.x = __shfl_xor_sync(0xffffffffu, r.x, 4);
    o.y = __shfl_xor_sync(0xffffffffu, r.y, 4);
    o.z = __shfl_xor_sync(0xffffffffu, r.z, 4);
    o.w = __shfl_xor_sync(0xffffffffu, r.w, 4);
    float4 h;
    h.x = 0.5f * (r.x + o.x);
    h.y = 0.5f * (r.y + o.y);
    h.z = 0.5f * (r.z + o.z);
    h.w = 0.5f * (r.w + o.w);
    if (lane < 4) {
        *(float4*)&out_agg[node * 16 + lane * 4] = h;   // agg_feature output
        float4 hs = make_float4(h.x * dv, h.y * dv, h.z * dv, h.w * dv);
        *(float4*)&g_hs[node * 16 + lane * 4] = hs;
    }
}

// ---------------- layer-2 aggregate ------------------------------------------
__global__ void __launch_bounds__(256) k_agg2() {
    int node = blockIdx.x * 8 + (threadIdx.x >> 5);
    int lane = threadIdx.x & 31;
    if (node >= NN) return;
    int beg = g_off[node], end = g_off[node + 1];
    int grp = lane >> 2;       // 0..7
    int cb = (lane & 3) * 4;   // column base 0..12

    float4 acc = make_float4(0.f, 0.f, 0.f, 0.f);
    int t = beg + grp;
    for (; t + 24 < end; t += 32) {
        int s0 = g_csrc[t];
        int s1 = g_csrc[t + 8];
        int s2 = g_csrc[t + 16];
        int s3 = g_csrc[t + 24];
        float4 a0 = *(const float4*)&g_hs[s0 * 16 + cb];
        float4 a1 = *(const float4*)&g_hs[s1 * 16 + cb];
        float4 a2 = *(const float4*)&g_hs[s2 * 16 + cb];
        float4 a3 = *(const float4*)&g_hs[s3 * 16 + cb];
        acc.x += (a0.x + a1.x) + (a2.x + a3.x);
        acc.y += (a0.y + a1.y) + (a2.y + a3.y);
        acc.z += (a0.z + a1.z) + (a2.z + a3.z);
        acc.w += (a0.w + a1.w) + (a2.w + a3.w);
    }
    for (; t < end; t += 8) {
        int s = g_csrc[t];
        float4 a = *(const float4*)&g_hs[s * 16 + cb];
        acc.x += a.x; acc.y += a.y; acc.z += a.z; acc.w += a.w;
    }
#pragma unroll
    for (int m = 4; m <= 16; m <<= 1) {
        acc.x += __shfl_xor_sync(0xffffffffu, acc.x, m);
        acc.y += __shfl_xor_sync(0xffffffffu, acc.y, m);
        acc.z += __shfl_xor_sync(0xffffffffu, acc.z, m);
        acc.w += __shfl_xor_sync(0xffffffffu, acc.w, m);
    }
    if (lane < 4) {
        float dv = g_dinv[node];
        float4 v = make_float4(acc.x * dv, acc.y * dv, acc.z * dv, acc.w * dv);
        *(float4*)&g_aggh[node * 16 + lane * 4] = v;
    }
}

// ---------------- layer-2 transform + log_softmax ----------------------------
__global__ void __launch_bounds__(256) k_final(const float* __restrict__ wi2,
                                               const float* __restrict__ wr2,
                                               const float* __restrict__ b2,
                                               const float* __restrict__ hsrc,
                                               float* __restrict__ out_logits) {
    __shared__ float Wi[256], Wr[256], Ba[16];
    int t = threadIdx.x;
    // K-mean commutes with identity activation -> average weights over stacks
    Wi[t] = 0.5f * (wi2[t] + wi2[256 + t]);
    Wr[t] = 0.5f * (wr2[t] + wr2[256 + t]);
    if (t < 16) Ba[t] = 0.5f * (b2[t] + b2[16 + t]);
    __syncthreads();

    int n = blockIdx.x * 256 + t;
    if (n >= NN) return;
    float g[16], h[16];
#pragma unroll
    for (int j = 0; j < 4; j++) {
        float4 gv = *(const float4*)&g_aggh[n * 16 + j * 4];
        float4 hv = *(const float4*)&hsrc[n * 16 + j * 4];
        g[j * 4 + 0] = gv.x; g[j * 4 + 1] = gv.y; g[j * 4 + 2] = gv.z; g[j * 4 + 3] = gv.w;
        h[j * 4 + 0] = hv.x; h[j * 4 + 1] = hv.y; h[j * 4 + 2] = hv.z; h[j * 4 + 3] = hv.w;
    }
    float l[16];
    float m = -1e30f;
#pragma unroll
    for (int o = 0; o < 16; o++) {
        float a = Ba[o];
#pragma unroll
        for (int ff = 0; ff < 16; ff++)
            a += g[ff] * Wi[ff * 16 + o] + h[ff] * Wr[ff * 16 + o];
        l[o] = a;
        m = fmaxf(m, a);
    }
    float s = 0.f;
#pragma unroll
    for (int o = 0; o < 16; o++) s += expf(l[o] - m);
    float ls = logf(s);
#pragma unroll
    for (int j = 0; j < 4; j++) {
        float4 v;
        v.x = l[j * 4 + 0] - m - ls;
        v.y = l[j * 4 + 1] - m - ls;
        v.z = l[j * 4 + 2] - m - ls;
        v.w = l[j * 4 + 3] - m - ls;
        *(float4*)&out_logits[n * 16 + j * 4] = v;
    }
}

// ---------------- launch -----------------------------------------------------
extern "C" void kernel_launch(void* const* d_in, const int* in_sizes, int n_in,
                              void* d_out, int out_size) {
    const float* x   = (const float*)d_in[0];
    const int*   ei  = (const int*)d_in[1];     // int32 (JAX x64 disabled)
    const float* wi1 = (const float*)d_in[2];
    const float* wr1 = (const float*)d_in[3];
    const float* b1  = (const float*)d_in[4];
    const float* wi2 = (const float*)d_in[5];
    const float* wr2 = (const float*)d_in[6];
    const float* b2  = (const float*)d_in[7];
    float* out        = (float*)d_out;
    float* out_logits = out;            // [N, 16] log_softmax
    float* out_agg    = out + NN * 16;  // [N, 16] agg_feature

    const int GEMM_BLOCKS = (NN / 16 + 7) / 8;   // 6250 warps / 8 per block

    bool dual = g_hx.ok;
    if (dual) {
        // Fork protocol: s2 MUST wait on a captured event before any launch,
        // so its work is part of the captured graph (R15 bug: missing fork).
        cudaEventRecord(g_hx.ev_fork, 0);
        cudaStreamWaitEvent(g_hx.s2, g_hx.ev_fork, 0);
        k_wprep<<<64, 256, 0, g_hx.s2>>>(wi1, wr1);              // #1
        // s0: CSR chain
        k_zero<<<(NN + 255) / 256, 256>>>();                     // #2
        k_hist<<<(EE / 4 + 255) / 256, 256>>>(ei);               // #3
        k_gemm1_tc<<<GEMM_BLOCKS, 256, 0, g_hx.s2>>>(x);         // #4 <- profiled
        k_scan_part<<<NB_SCAN, 256>>>();                         // #5
        cudaEventRecord(g_hx.ev_dinv, 0);
        k_scan_top<<<1, 512>>>();                                // #6
        k_scan_out<<<NB_SCAN, 256>>>();                          // #7
        k_csr<<<(EE / 4 + 255) / 256, 256>>>(ei);                // #8
        // s2: scale needs dinv (and gemm, same stream)
        cudaStreamWaitEvent(g_hx.s2, g_hx.ev_dinv, 0);
        k_scale<<<(NN * 8 + 255) / 256, 256, 0, g_hx.s2>>>();    // #9
        cudaEventRecord(g_hx.ev_join, g_hx.s2);
        cudaStreamWaitEvent(0, g_hx.ev_join, 0);
    } else {
        k_wprep<<<64, 256>>>(wi1, wr1);
        k_zero<<<(NN + 255) / 256, 256>>>();
        k_hist<<<(EE / 4 + 255) / 256, 256>>>(ei);
        k_gemm1_tc<<<GEMM_BLOCKS, 256>>>(x);
        k_scan_part<<<NB_SCAN, 256>>>();
        k_scan_top<<<1, 512>>>();
        k_scan_out<<<NB_SCAN, 256>>>();
        k_csr<<<(EE / 4 + 255) / 256, 256>>>(ei);
        k_scale<<<(NN * 8 + 255) / 256, 256>>>();
    }

    k_agg1<<<(NN + 7) / 8, 256>>>(b1, out_agg);
    k_agg2<<<(NN + 7) / 8, 256>>>();
    k_final<<<(NN + 255) / 256, 256>>>(wi2, wr2, b2, out_agg, out_logits);
}